// round 13
// baseline (speedup 1.0000x reference)
#include <cuda_runtime.h>
#include <cuda_bf16.h>
#include <math.h>

#define Bv    8
#define Sv    4096
#define Tv    512
#define HIDv  512
#define HEADSv 8
#define DKv   64

typedef unsigned long long u64;

// ------------------------- scratch (__device__ globals) --------------------
__device__ float g_Q[Bv * Tv * HIDv];
__device__ float g_K[Bv * Sv * HIDv];
__device__ float g_V[Bv * Sv * HIDv];
__device__ float g_ctx[Bv * Tv * HIDv];
__device__ __nv_bfloat16 g_in_hi[Bv * Sv * HIDv];
__device__ __nv_bfloat16 g_in_lo[Bv * Sv * HIDv];
__device__ __nv_bfloat16 g_tg_hi[Bv * Tv * HIDv];
__device__ __nv_bfloat16 g_tg_lo[Bv * Tv * HIDv];
__device__ __nv_bfloat16 g_cx_hi[Bv * Tv * HIDv];
__device__ __nv_bfloat16 g_cx_lo[Bv * Tv * HIDv];
__device__ __nv_bfloat16 g_w_hi[4 * HIDv * HIDv];
__device__ __nv_bfloat16 g_w_lo[4 * HIDv * HIDv];

// ---------------- packed f32x2 helpers (FFMA2, attention) ------------------
__device__ __forceinline__ u64 pack2(float x, float y) {
    u64 d; asm("mov.b64 %0, {%1, %2};" : "=l"(d) : "f"(x), "f"(y)); return d;
}
__device__ __forceinline__ u64 pdup(float x) { return pack2(x, x); }
__device__ __forceinline__ void unpack2(u64 v, float& x, float& y) {
    asm("mov.b64 {%0, %1}, %2;" : "=f"(x), "=f"(y) : "l"(v));
}
__device__ __forceinline__ u64 fma2(u64 a, u64 b, u64 c) {
    u64 d; asm("fma.rn.f32x2 %0, %1, %2, %3;" : "=l"(d) : "l"(a), "l"(b), "l"(c)); return d;
}
__device__ __forceinline__ u64 mul2(u64 a, u64 b) {
    u64 d; asm("mul.rn.f32x2 %0, %1, %2;" : "=l"(d) : "l"(a), "l"(b)); return d;
}
__device__ __forceinline__ float fast_exp(float x) {
    float y = fmaxf(x * 1.4426950408889634f, -126.0f);
    float n = rintf(y);
    float r = y - n;
    float q = 1.5403530394e-4f;
    q = fmaf(q, r, 1.3333558146e-3f);
    q = fmaf(q, r, 9.6181291076e-3f);
    q = fmaf(q, r, 5.5504108664e-2f);
    q = fmaf(q, r, 2.4022650696e-1f);
    q = fmaf(q, r, 6.9314718056e-1f);
    q = fmaf(q, r, 1.0f);
    return q * __int_as_float(((int)n + 127) << 23);
}

// ---------------- mma.sync + cp.async helpers (portable PTX) ---------------
__device__ __forceinline__ void ldm_x4(unsigned* r, unsigned saddr) {
    asm volatile("ldmatrix.sync.aligned.m8n8.x4.shared.b16 {%0,%1,%2,%3}, [%4];"
                 : "=r"(r[0]), "=r"(r[1]), "=r"(r[2]), "=r"(r[3]) : "r"(saddr));
}
__device__ __forceinline__ void mma_bf16(float* d, const unsigned* a, const unsigned* b) {
    asm volatile(
        "mma.sync.aligned.m16n8k16.row.col.f32.bf16.bf16.f32 "
        "{%0,%1,%2,%3}, {%4,%5,%6,%7}, {%8,%9}, {%0,%1,%2,%3};"
        : "+f"(d[0]), "+f"(d[1]), "+f"(d[2]), "+f"(d[3])
        : "r"(a[0]), "r"(a[1]), "r"(a[2]), "r"(a[3]), "r"(b[0]), "r"(b[1]));
}
__device__ __forceinline__ void cp16(void* sdst, const void* gsrc) {
    unsigned s = (unsigned)__cvta_generic_to_shared(sdst);
    asm volatile("cp.async.ca.shared.global [%0], [%1], 16;" :: "r"(s), "l"(gsrc) : "memory");
}
__device__ __forceinline__ void cp_commit() {
    asm volatile("cp.async.commit_group;" ::: "memory");
}
template <int N> __device__ __forceinline__ void cp_wait() {
    asm volatile("cp.async.wait_group %0;" :: "n"(N) : "memory");
}

// ---------------------------------------------------------------------------
// fp32 -> (hi, lo) bf16 split, vectorized.
// ---------------------------------------------------------------------------
__global__ void cvt_kernel(const float* __restrict__ x,
                           __nv_bfloat16* __restrict__ hi,
                           __nv_bfloat16* __restrict__ lo, int n4)
{
    int i = blockIdx.x * blockDim.x + threadIdx.x;
    if (i >= n4) return;
    float4 v = ((const float4*)x)[i];
    __nv_bfloat16 h0 = __float2bfloat16(v.x);
    __nv_bfloat16 h1 = __float2bfloat16(v.y);
    __nv_bfloat16 h2 = __float2bfloat16(v.z);
    __nv_bfloat16 h3 = __float2bfloat16(v.w);
    __nv_bfloat16 l0 = __float2bfloat16(v.x - __bfloat162float(h0));
    __nv_bfloat16 l1 = __float2bfloat16(v.y - __bfloat162float(h1));
    __nv_bfloat16 l2 = __float2bfloat16(v.z - __bfloat162float(h2));
    __nv_bfloat16 l3 = __float2bfloat16(v.w - __bfloat162float(h3));
    ((__nv_bfloat162*)hi)[2 * i]     = __halves2bfloat162(h0, h1);
    ((__nv_bfloat162*)hi)[2 * i + 1] = __halves2bfloat162(h2, h3);
    ((__nv_bfloat162*)lo)[2 * i]     = __halves2bfloat162(l0, l1);
    ((__nv_bfloat162*)lo)[2 * i + 1] = __halves2bfloat162(l2, l3);
}

// ---------------------------------------------------------------------------
// HMMA GEMM, 2-stage cp.async double buffer.
// C[M,512] = A[M,512] @ W[512,512]^T + bias, bf16-split 3 terms.
// Grid (4, M/128); CTA tile 128x128, BK=64; 8 warps (2x4), warp tile 64x32.
// smem: 2 stages x 4 arrays x 128 x GP bf16 = 147456 B -> 1 CTA/SM, but
// chunk c+1 streams in via cp.async while chunk c runs on the tensor pipes.
// ---------------------------------------------------------------------------
#define GP 72                              // smem row pitch in bf16
#define STG_ELEMS (128 * GP)               // one array, one stage
#define STAGE_ELEMS (4 * STG_ELEMS)        // Ahi,Alo,Whi,Wlo
#define GSMEM (2 * STAGE_ELEMS * 2)        // bytes

__global__ __launch_bounds__(256) void hmma_gemm(
    const __nv_bfloat16* __restrict__ Ahi, const __nv_bfloat16* __restrict__ Alo,
    const __nv_bfloat16* __restrict__ Whi, const __nv_bfloat16* __restrict__ Wlo,
    const float* __restrict__ bias, float* __restrict__ C)
{
    extern __shared__ __nv_bfloat16 sb16[];

    const int tid  = threadIdx.x;
    const int w    = tid >> 5, lane = tid & 31;
    const int wm   = w >> 2, wn = w & 3;
    const int m0   = blockIdx.y * 128;
    const int n0   = blockIdx.x * 128;

    const int aRow = wm * 64 + ((lane >> 3) & 1) * 8 + (lane & 7);  // + mi*16
    const int aK   = (lane >> 4) * 8;                               // + ks*16
    const int bRow = wn * 32 + (lane >> 4) * 8 + (lane & 7);        // + pr*16
    const int bK   = ((lane >> 3) & 1) * 8;                         // + ks*16

    // issue one chunk's loads into stage st
    auto issue = [&](int c, int st) {
        const int k0 = c * 64;
        __nv_bfloat16* sA_hi = sb16 + st * STAGE_ELEMS;
        __nv_bfloat16* sA_lo = sA_hi + STG_ELEMS;
        __nv_bfloat16* sW_hi = sA_lo + STG_ELEMS;
        __nv_bfloat16* sW_lo = sW_hi + STG_ELEMS;
        #pragma unroll
        for (int it = 0; it < 4; it++) {
            int idx = tid + it * 256;            // 0..1023
            int row = idx >> 3;                  // 0..127
            int sg  = (idx & 7) * 8;             // bf16 offset (16B segs)
            size_t ga = (size_t)(m0 + row) * 512 + k0 + sg;
            size_t gw = (size_t)(n0 + row) * 512 + k0 + sg;
            cp16(&sA_hi[row * GP + sg], &Ahi[ga]);
            cp16(&sA_lo[row * GP + sg], &Alo[ga]);
            cp16(&sW_hi[row * GP + sg], &Whi[gw]);
            cp16(&sW_lo[row * GP + sg], &Wlo[gw]);
        }
    };

    float acc[4][4][4];
    #pragma unroll
    for (int i = 0; i < 4; i++)
        #pragma unroll
        for (int j = 0; j < 4; j++)
            #pragma unroll
            for (int r = 0; r < 4; r++) acc[i][j][r] = 0.0f;

    issue(0, 0);
    cp_commit();

    for (int c = 0; c < 8; c++) {
        const int st = c & 1;
        if (c < 7) { issue(c + 1, st ^ 1); cp_commit(); cp_wait<1>(); }
        else       { cp_wait<0>(); }
        __syncthreads();

        const unsigned uAhi = (unsigned)__cvta_generic_to_shared(sb16 + st * STAGE_ELEMS);
        const unsigned uAlo = uAhi + STG_ELEMS * 2;
        const unsigned uWhi = uAlo + STG_ELEMS * 2;
        const unsigned uWlo = uWhi + STG_ELEMS * 2;

        #pragma unroll
        for (int ks = 0; ks < 4; ks++) {
            unsigned ah[4][4], bh[4][2], bl[4][2];
            #pragma unroll
            for (int mi = 0; mi < 4; mi++)
                ldm_x4(ah[mi], uAhi + (unsigned)(((aRow + mi * 16) * GP + ks * 16 + aK) * 2));
            #pragma unroll
            for (int pr = 0; pr < 2; pr++) {
                unsigned t[4];
                ldm_x4(t, uWhi + (unsigned)(((bRow + pr * 16) * GP + ks * 16 + bK) * 2));
                bh[2 * pr][0] = t[0]; bh[2 * pr][1] = t[1];
                bh[2 * pr + 1][0] = t[2]; bh[2 * pr + 1][1] = t[3];
                ldm_x4(t, uWlo + (unsigned)(((bRow + pr * 16) * GP + ks * 16 + bK) * 2));
                bl[2 * pr][0] = t[0]; bl[2 * pr][1] = t[1];
                bl[2 * pr + 1][0] = t[2]; bl[2 * pr + 1][1] = t[3];
            }
            #pragma unroll
            for (int mi = 0; mi < 4; mi++)
                #pragma unroll
                for (int ns = 0; ns < 4; ns++) {
                    mma_bf16(acc[mi][ns], ah[mi], bh[ns]);   // hi*hi
                    mma_bf16(acc[mi][ns], ah[mi], bl[ns]);   // hi*lo
                }
            unsigned al[4][4];
            #pragma unroll
            for (int mi = 0; mi < 4; mi++)
                ldm_x4(al[mi], uAlo + (unsigned)(((aRow + mi * 16) * GP + ks * 16 + aK) * 2));
            #pragma unroll
            for (int mi = 0; mi < 4; mi++)
                #pragma unroll
                for (int ns = 0; ns < 4; ns++)
                    mma_bf16(acc[mi][ns], al[mi], bh[ns]);   // lo*hi
        }
        __syncthreads();
    }

    // epilogue
    const int g  = lane >> 2, tg = lane & 3;
    #pragma unroll
    for (int mi = 0; mi < 4; mi++) {
        #pragma unroll
        for (int ns = 0; ns < 4; ns++) {
            int row = m0 + wm * 64 + mi * 16 + g;
            int col = n0 + wn * 32 + ns * 8 + tg * 2;
            float2 bb = *(const float2*)&bias[col];
            float2 v0 = {acc[mi][ns][0] + bb.x, acc[mi][ns][1] + bb.y};
            float2 v1 = {acc[mi][ns][2] + bb.x, acc[mi][ns][3] + bb.y};
            *(float2*)&C[(size_t)row * 512 + col]       = v0;
            *(float2*)&C[(size_t)(row + 8) * 512 + col] = v1;
        }
    }
}

// ---------------------------------------------------------------------------
// Flash attention: 128-query tiles, 2 CTAs/SM (UNCHANGED from round 11/12).
// ---------------------------------------------------------------------------
__global__ __launch_bounds__(256, 2) void attn_kernel(const int* __restrict__ mask)
{
    extern __shared__ float sm[];
    float* Qs   = sm;                    // [64][132]  Q k-major
    float* Ks   = Qs + 64 * 132;         // [64][68]   K k-major
    float* Vs   = Ks + 64 * 68;          // [64][68]   V s-major
    float* Ps   = Vs + 64 * 68;          // [64][132]  P s-major (swizzled cols)
    float* mneg = Ps + 64 * 132;         // [64]

    const int tid = threadIdx.x;
    const int tx = tid & 7;
    const int ty = tid >> 3;             // 0..31, 4 queries each
    const int t0 = blockIdx.x * 128;
    const int h  = blockIdx.y;
    const int b  = blockIdx.z;

    #pragma unroll
    for (int r = 0; r < 8; r++) {
        int idx = tid + r * 256;
        int row = idx >> 4;              // 0..127
        int c4  = (idx & 15) * 4;
        float4 q = *(const float4*)&g_Q[((size_t)(b * Tv + t0 + row)) * HIDv + h * DKv + c4];
        Qs[(c4 + 0) * 132 + row] = q.x;
        Qs[(c4 + 1) * 132 + row] = q.y;
        Qs[(c4 + 2) * 132 + row] = q.z;
        Qs[(c4 + 3) * 132 + row] = q.w;
    }

    float rowM[4], rowL[4];
    #pragma unroll
    for (int i = 0; i < 4; i++) { rowM[i] = -1e30f; rowL[i] = 0.0f; }

    u64 acc2[4][4];
    #pragma unroll
    for (int i = 0; i < 4; i++)
        #pragma unroll
        for (int j = 0; j < 4; j++) acc2[i][j] = 0ull;

    const int Xst = (tx & 3) << 2;
    __syncthreads();

    for (int s0 = 0; s0 < Sv; s0 += 64) {
        #pragma unroll
        for (int r = 0; r < 4; r++) {
            int idx = tid + r * 256;
            int row = idx >> 4;
            int c4  = (idx & 15) * 4;
            size_t g = ((size_t)(b * Sv + s0 + row)) * HIDv + h * DKv + c4;
            float4 k = *(const float4*)&g_K[g];
            Ks[(c4 + 0) * 68 + row] = k.x;
            Ks[(c4 + 1) * 68 + row] = k.y;
            Ks[(c4 + 2) * 68 + row] = k.z;
            Ks[(c4 + 3) * 68 + row] = k.w;
            float4 v = *(const float4*)&g_V[g];
            *(float4*)&Vs[row * 68 + c4] = v;
        }
        if (tid < 64) mneg[tid] = (mask[b * Sv + s0 + tid] != 0) ? 0.0f : -1e20f;
        __syncthreads();

        u64 sc2[4][4];
        #pragma unroll
        for (int i = 0; i < 4; i++)
            #pragma unroll
            for (int j = 0; j < 4; j++) sc2[i][j] = 0ull;

        #pragma unroll 8
        for (int kk = 0; kk < 64; kk++) {
            float4 a0 = *(const float4*)&Qs[kk * 132 + ty * 4];
            ulonglong2 b0 = *(const ulonglong2*)&Ks[kk * 68 + tx * 8];
            ulonglong2 b1 = *(const ulonglong2*)&Ks[kk * 68 + tx * 8 + 4];
            u64 bb2[4] = {b0.x, b0.y, b1.x, b1.y};
            u64 a2[4];
            a2[0] = pdup(a0.x); a2[1] = pdup(a0.y);
            a2[2] = pdup(a0.z); a2[3] = pdup(a0.w);
            #pragma unroll
            for (int i = 0; i < 4; i++)
                #pragma unroll
                for (int j = 0; j < 4; j++)
                    sc2[i][j] = fma2(a2[i], bb2[j], sc2[i][j]);
        }

        {
            ulonglong2 m0 = *(const ulonglong2*)&mneg[tx * 8];
            ulonglong2 m1 = *(const ulonglong2*)&mneg[tx * 8 + 4];
            u64 mm[4] = {m0.x, m0.y, m1.x, m1.y};
            u64 c18 = pdup(0.125f);
            #pragma unroll
            for (int i = 0; i < 4; i++)
                #pragma unroll
                for (int j = 0; j < 4; j++)
                    sc2[i][j] = fma2(sc2[i][j], c18, mm[j]);
        }

        #pragma unroll
        for (int i = 0; i < 4; i++) {
            float s8[8];
            unpack2(sc2[i][0], s8[0], s8[1]);
            unpack2(sc2[i][1], s8[2], s8[3]);
            unpack2(sc2[i][2], s8[4], s8[5]);
            unpack2(sc2[i][3], s8[6], s8[7]);
            float mx = fmaxf(fmaxf(fmaxf(s8[0], s8[1]), fmaxf(s8[2], s8[3])),
                             fmaxf(fmaxf(s8[4], s8[5]), fmaxf(s8[6], s8[7])));
            #pragma unroll
            for (int o = 4; o >= 1; o >>= 1)
                mx = fmaxf(mx, __shfl_xor_sync(0xffffffffu, mx, o, 8));

            float mnw = fmaxf(rowM[i], mx);
            float f   = fast_exp(rowM[i] - mnw);
            rowM[i] = mnw;

            float p[8], se = 0.0f;
            #pragma unroll
            for (int k = 0; k < 8; k++) { p[k] = fast_exp(s8[k] - mnw); se += p[k]; }
            #pragma unroll
            for (int o = 4; o >= 1; o >>= 1)
                se += __shfl_xor_sync(0xffffffffu, se, o, 8);
            rowL[i] = rowL[i] * f + se;

            u64 f2 = pdup(f);
            #pragma unroll
            for (int j = 0; j < 4; j++) acc2[i][j] = mul2(acc2[i][j], f2);

            int colp = (ty * 4 + i) ^ Xst;
            #pragma unroll
            for (int j = 0; j < 8; j++)
                Ps[(tx * 8 + j) * 132 + colp] = p[j];
        }
        __syncthreads();

        #pragma unroll 4
        for (int s = 0; s < 64; s++) {
            int X = ((s >> 3) & 3) << 2;
            float4 pq = *(const float4*)&Ps[s * 132 + ((ty * 4) ^ X)];
            u64 pp[4] = {pdup(pq.x), pdup(pq.y), pdup(pq.z), pdup(pq.w)};
            ulonglong2 v0 = *(const ulonglong2*)&Vs[s * 68 + tx * 8];
            ulonglong2 v1 = *(const ulonglong2*)&Vs[s * 68 + tx * 8 + 4];
            u64 vv[4] = {v0.x, v0.y, v1.x, v1.y};
            #pragma unroll
            for (int i = 0; i < 4; i++)
                #pragma unroll
                for (int j = 0; j < 4; j++)
                    acc2[i][j] = fma2(pp[i], vv[j], acc2[i][j]);
        }
        __syncthreads();
    }

    #pragma unroll
    for (int i = 0; i < 4; i++) {
        float inv = 1.0f / rowL[i];
        float o[8];
        unpack2(acc2[i][0], o[0], o[1]);
        unpack2(acc2[i][1], o[2], o[3]);
        unpack2(acc2[i][2], o[4], o[5]);
        unpack2(acc2[i][3], o[6], o[7]);
        float4 s0, s1;
        s0.x = o[0] * inv; s0.y = o[1] * inv; s0.z = o[2] * inv; s0.w = o[3] * inv;
        s1.x = o[4] * inv; s1.y = o[5] * inv; s1.z = o[6] * inv; s1.w = o[7] * inv;
        size_t base = ((size_t)(b * Tv + t0 + ty * 4 + i)) * HIDv + h * DKv + tx * 8;
        *(float4*)&g_ctx[base]     = s0;
        *(float4*)&g_ctx[base + 4] = s1;
    }
}

// ---------------------------------------------------------------------------

extern "C" void kernel_launch(void* const* d_in, const int* in_sizes, int n_in,
                              void* d_out, int out_size)
{
    const float* inputs  = (const float*)d_in[0];
    const float* targets = (const float*)d_in[1];
    const int*   mask    = (const int*)d_in[2];     // bool widened to int32
    const float* Wq = (const float*)d_in[3];
    const float* bq = (const float*)d_in[4];
    const float* Wk = (const float*)d_in[5];
    const float* bk = (const float*)d_in[6];
    const float* Wv = (const float*)d_in[7];
    const float* bv = (const float*)d_in[8];
    const float* Wo = (const float*)d_in[9];
    const float* bo = (const float*)d_in[10];
    float* out = (float*)d_out;

    float *pQ, *pK, *pV, *pC;
    cudaGetSymbolAddress((void**)&pQ, g_Q);
    cudaGetSymbolAddress((void**)&pK, g_K);
    cudaGetSymbolAddress((void**)&pV, g_V);
    cudaGetSymbolAddress((void**)&pC, g_ctx);
    __nv_bfloat16 *inH, *inL, *tgH, *tgL, *cxH, *cxL, *wH, *wL;
    cudaGetSymbolAddress((void**)&inH, g_in_hi);
    cudaGetSymbolAddress((void**)&inL, g_in_lo);
    cudaGetSymbolAddress((void**)&tgH, g_tg_hi);
    cudaGetSymbolAddress((void**)&tgL, g_tg_lo);
    cudaGetSymbolAddress((void**)&cxH, g_cx_hi);
    cudaGetSymbolAddress((void**)&cxL, g_cx_lo);
    cudaGetSymbolAddress((void**)&wH, g_w_hi);
    cudaGetSymbolAddress((void**)&wL, g_w_lo);

    const int ATTN_SMEM = (64 * 132 + 64 * 68 + 64 * 68 + 64 * 132 + 64) * (int)sizeof(float);
    cudaFuncSetAttribute(attn_kernel, cudaFuncAttributeMaxDynamicSharedMemorySize, ATTN_SMEM);
    cudaFuncSetAttribute(hmma_gemm, cudaFuncAttributeMaxDynamicSharedMemorySize, GSMEM);

    const int W_ELEMS = HIDv * HIDv;
    // The ncu capture lands on the 4th kernel launch -> make that hmma K.
    cvt_kernel<<<(Bv * Sv * HIDv / 4 + 255) / 256, 256>>>(inputs, inH, inL, Bv * Sv * HIDv / 4);
    cvt_kernel<<<(W_ELEMS / 4 + 255) / 256, 256>>>(Wk, wH + 1 * W_ELEMS, wL + 1 * W_ELEMS, W_ELEMS / 4);
    cvt_kernel<<<(W_ELEMS / 4 + 255) / 256, 256>>>(Wv, wH + 2 * W_ELEMS, wL + 2 * W_ELEMS, W_ELEMS / 4);

    hmma_gemm<<<dim3(4, Bv * Sv / 128), 256, GSMEM>>>(inH, inL, wH + 1 * W_ELEMS, wL + 1 * W_ELEMS, bk, pK);  // 4th: captured
    hmma_gemm<<<dim3(4, Bv * Sv / 128), 256, GSMEM>>>(inH, inL, wH + 2 * W_ELEMS, wL + 2 * W_ELEMS, bv, pV);

    cvt_kernel<<<(Bv * Tv * HIDv / 4 + 255) / 256, 256>>>(targets, tgH, tgL, Bv * Tv * HIDv / 4);
    cvt_kernel<<<(W_ELEMS / 4 + 255) / 256, 256>>>(Wq, wH + 0 * W_ELEMS, wL + 0 * W_ELEMS, W_ELEMS / 4);
    hmma_gemm<<<dim3(4, Bv * Tv / 128), 256, GSMEM>>>(tgH, tgL, wH + 0 * W_ELEMS, wL + 0 * W_ELEMS, bq, pQ);

    attn_kernel<<<dim3(Tv / 128, HEADSv, Bv), 256, ATTN_SMEM>>>(mask);

    cvt_kernel<<<(Bv * Tv * HIDv / 4 + 255) / 256, 256>>>(pC, cxH, cxL, Bv * Tv * HIDv / 4);
    cvt_kernel<<<(W_ELEMS / 4 + 255) / 256, 256>>>(Wo, wH + 3 * W_ELEMS, wL + 3 * W_ELEMS, W_ELEMS / 4);
    hmma_gemm<<<dim3(4, Bv * Tv / 128), 256, GSMEM>>>(cxH, cxL, wH + 3 * W_ELEMS, wL + 3 * W_ELEMS, bo, out);
}

// round 14
// speedup vs baseline: 1.3393x; 1.3393x over previous
#include <cuda_runtime.h>
#include <cuda_bf16.h>
#include <math.h>

#define Bv    8
#define Sv    4096
#define Tv    512
#define HIDv  512
#define HEADSv 8
#define DKv   64

typedef unsigned long long u64;

// ------------------------- scratch (__device__ globals) --------------------
__device__ float g_Q[Bv * Tv * HIDv];
__device__ float g_K[Bv * Sv * HIDv];
__device__ float g_V[Bv * Sv * HIDv];
__device__ float g_ctx[Bv * Tv * HIDv];
__device__ __nv_bfloat16 g_in_hi[Bv * Sv * HIDv];
__device__ __nv_bfloat16 g_in_lo[Bv * Sv * HIDv];
__device__ __nv_bfloat16 g_tg_hi[Bv * Tv * HIDv];
__device__ __nv_bfloat16 g_tg_lo[Bv * Tv * HIDv];
__device__ __nv_bfloat16 g_cx_hi[Bv * Tv * HIDv];
__device__ __nv_bfloat16 g_cx_lo[Bv * Tv * HIDv];
__device__ __nv_bfloat16 g_w_hi[4 * HIDv * HIDv];
__device__ __nv_bfloat16 g_w_lo[4 * HIDv * HIDv];

// ---------------- packed f32x2 helpers (FFMA2, attention) ------------------
__device__ __forceinline__ u64 pack2(float x, float y) {
    u64 d; asm("mov.b64 %0, {%1, %2};" : "=l"(d) : "f"(x), "f"(y)); return d;
}
__device__ __forceinline__ u64 pdup(float x) { return pack2(x, x); }
__device__ __forceinline__ void unpack2(u64 v, float& x, float& y) {
    asm("mov.b64 {%0, %1}, %2;" : "=f"(x), "=f"(y) : "l"(v));
}
__device__ __forceinline__ u64 fma2(u64 a, u64 b, u64 c) {
    u64 d; asm("fma.rn.f32x2 %0, %1, %2, %3;" : "=l"(d) : "l"(a), "l"(b), "l"(c)); return d;
}
__device__ __forceinline__ u64 mul2(u64 a, u64 b) {
    u64 d; asm("mul.rn.f32x2 %0, %1, %2;" : "=l"(d) : "l"(a), "l"(b)); return d;
}
__device__ __forceinline__ float fast_exp(float x) {
    float y = fmaxf(x * 1.4426950408889634f, -126.0f);
    float n = rintf(y);
    float r = y - n;
    float q = 1.5403530394e-4f;
    q = fmaf(q, r, 1.3333558146e-3f);
    q = fmaf(q, r, 9.6181291076e-3f);
    q = fmaf(q, r, 5.5504108664e-2f);
    q = fmaf(q, r, 2.4022650696e-1f);
    q = fmaf(q, r, 6.9314718056e-1f);
    q = fmaf(q, r, 1.0f);
    return q * __int_as_float(((int)n + 127) << 23);
}

// ---------------- mma.sync + cp.async helpers (portable PTX) ---------------
__device__ __forceinline__ void ldm_x4(unsigned* r, unsigned saddr) {
    asm volatile("ldmatrix.sync.aligned.m8n8.x4.shared.b16 {%0,%1,%2,%3}, [%4];"
                 : "=r"(r[0]), "=r"(r[1]), "=r"(r[2]), "=r"(r[3]) : "r"(saddr));
}
__device__ __forceinline__ void mma_bf16(float* d, const unsigned* a, const unsigned* b) {
    asm volatile(
        "mma.sync.aligned.m16n8k16.row.col.f32.bf16.bf16.f32 "
        "{%0,%1,%2,%3}, {%4,%5,%6,%7}, {%8,%9}, {%0,%1,%2,%3};"
        : "+f"(d[0]), "+f"(d[1]), "+f"(d[2]), "+f"(d[3])
        : "r"(a[0]), "r"(a[1]), "r"(a[2]), "r"(a[3]), "r"(b[0]), "r"(b[1]));
}
__device__ __forceinline__ void cp16(void* sdst, const void* gsrc) {
    unsigned s = (unsigned)__cvta_generic_to_shared(sdst);
    asm volatile("cp.async.ca.shared.global [%0], [%1], 16;" :: "r"(s), "l"(gsrc) : "memory");
}
__device__ __forceinline__ void cp_commit() {
    asm volatile("cp.async.commit_group;" ::: "memory");
}
template <int N> __device__ __forceinline__ void cp_wait() {
    asm volatile("cp.async.wait_group %0;" :: "n"(N) : "memory");
}

// ---------------------------------------------------------------------------
// fp32 -> (hi, lo) bf16 split, vectorized.
// ---------------------------------------------------------------------------
__global__ void cvt_kernel(const float* __restrict__ x,
                           __nv_bfloat16* __restrict__ hi,
                           __nv_bfloat16* __restrict__ lo, int n4)
{
    int i = blockIdx.x * blockDim.x + threadIdx.x;
    if (i >= n4) return;
    float4 v = ((const float4*)x)[i];
    __nv_bfloat16 h0 = __float2bfloat16(v.x);
    __nv_bfloat16 h1 = __float2bfloat16(v.y);
    __nv_bfloat16 h2 = __float2bfloat16(v.z);
    __nv_bfloat16 h3 = __float2bfloat16(v.w);
    __nv_bfloat16 l0 = __float2bfloat16(v.x - __bfloat162float(h0));
    __nv_bfloat16 l1 = __float2bfloat16(v.y - __bfloat162float(h1));
    __nv_bfloat16 l2 = __float2bfloat16(v.z - __bfloat162float(h2));
    __nv_bfloat16 l3 = __float2bfloat16(v.w - __bfloat162float(h3));
    ((__nv_bfloat162*)hi)[2 * i]     = __halves2bfloat162(h0, h1);
    ((__nv_bfloat162*)hi)[2 * i + 1] = __halves2bfloat162(h2, h3);
    ((__nv_bfloat162*)lo)[2 * i]     = __halves2bfloat162(l0, l1);
    ((__nv_bfloat162*)lo)[2 * i + 1] = __halves2bfloat162(l2, l3);
}

// ---------------------------------------------------------------------------
// HMMA GEMM, 2-stage cp.async double buffer (UNCHANGED from round 13).
// C[M,512] = A[M,512] @ W[512,512]^T + bias, bf16-split 3 terms.
// ---------------------------------------------------------------------------
#define GP 72                              // smem row pitch in bf16
#define STG_ELEMS (128 * GP)
#define STAGE_ELEMS (4 * STG_ELEMS)
#define GSMEM (2 * STAGE_ELEMS * 2)

__global__ __launch_bounds__(256) void hmma_gemm(
    const __nv_bfloat16* __restrict__ Ahi, const __nv_bfloat16* __restrict__ Alo,
    const __nv_bfloat16* __restrict__ Whi, const __nv_bfloat16* __restrict__ Wlo,
    const float* __restrict__ bias, float* __restrict__ C)
{
    extern __shared__ __nv_bfloat16 sb16[];

    const int tid  = threadIdx.x;
    const int w    = tid >> 5, lane = tid & 31;
    const int wm   = w >> 2, wn = w & 3;
    const int m0   = blockIdx.y * 128;
    const int n0   = blockIdx.x * 128;

    const int aRow = wm * 64 + ((lane >> 3) & 1) * 8 + (lane & 7);
    const int aK   = (lane >> 4) * 8;
    const int bRow = wn * 32 + (lane >> 4) * 8 + (lane & 7);
    const int bK   = ((lane >> 3) & 1) * 8;

    auto issue = [&](int c, int st) {
        const int k0 = c * 64;
        __nv_bfloat16* sA_hi = sb16 + st * STAGE_ELEMS;
        __nv_bfloat16* sA_lo = sA_hi + STG_ELEMS;
        __nv_bfloat16* sW_hi = sA_lo + STG_ELEMS;
        __nv_bfloat16* sW_lo = sW_hi + STG_ELEMS;
        #pragma unroll
        for (int it = 0; it < 4; it++) {
            int idx = tid + it * 256;
            int row = idx >> 3;
            int sg  = (idx & 7) * 8;
            size_t ga = (size_t)(m0 + row) * 512 + k0 + sg;
            size_t gw = (size_t)(n0 + row) * 512 + k0 + sg;
            cp16(&sA_hi[row * GP + sg], &Ahi[ga]);
            cp16(&sA_lo[row * GP + sg], &Alo[ga]);
            cp16(&sW_hi[row * GP + sg], &Whi[gw]);
            cp16(&sW_lo[row * GP + sg], &Wlo[gw]);
        }
    };

    float acc[4][4][4];
    #pragma unroll
    for (int i = 0; i < 4; i++)
        #pragma unroll
        for (int j = 0; j < 4; j++)
            #pragma unroll
            for (int r = 0; r < 4; r++) acc[i][j][r] = 0.0f;

    issue(0, 0);
    cp_commit();

    for (int c = 0; c < 8; c++) {
        const int st = c & 1;
        if (c < 7) { issue(c + 1, st ^ 1); cp_commit(); cp_wait<1>(); }
        else       { cp_wait<0>(); }
        __syncthreads();

        const unsigned uAhi = (unsigned)__cvta_generic_to_shared(sb16 + st * STAGE_ELEMS);
        const unsigned uAlo = uAhi + STG_ELEMS * 2;
        const unsigned uWhi = uAlo + STG_ELEMS * 2;
        const unsigned uWlo = uWhi + STG_ELEMS * 2;

        #pragma unroll
        for (int ks = 0; ks < 4; ks++) {
            unsigned ah[4][4], bh[4][2], bl[4][2];
            #pragma unroll
            for (int mi = 0; mi < 4; mi++)
                ldm_x4(ah[mi], uAhi + (unsigned)(((aRow + mi * 16) * GP + ks * 16 + aK) * 2));
            #pragma unroll
            for (int pr = 0; pr < 2; pr++) {
                unsigned t[4];
                ldm_x4(t, uWhi + (unsigned)(((bRow + pr * 16) * GP + ks * 16 + bK) * 2));
                bh[2 * pr][0] = t[0]; bh[2 * pr][1] = t[1];
                bh[2 * pr + 1][0] = t[2]; bh[2 * pr + 1][1] = t[3];
                ldm_x4(t, uWlo + (unsigned)(((bRow + pr * 16) * GP + ks * 16 + bK) * 2));
                bl[2 * pr][0] = t[0]; bl[2 * pr][1] = t[1];
                bl[2 * pr + 1][0] = t[2]; bl[2 * pr + 1][1] = t[3];
            }
            #pragma unroll
            for (int mi = 0; mi < 4; mi++)
                #pragma unroll
                for (int ns = 0; ns < 4; ns++) {
                    mma_bf16(acc[mi][ns], ah[mi], bh[ns]);   // hi*hi
                    mma_bf16(acc[mi][ns], ah[mi], bl[ns]);   // hi*lo
                }
            unsigned al[4][4];
            #pragma unroll
            for (int mi = 0; mi < 4; mi++)
                ldm_x4(al[mi], uAlo + (unsigned)(((aRow + mi * 16) * GP + ks * 16 + aK) * 2));
            #pragma unroll
            for (int mi = 0; mi < 4; mi++)
                #pragma unroll
                for (int ns = 0; ns < 4; ns++)
                    mma_bf16(acc[mi][ns], al[mi], bh[ns]);   // lo*hi
        }
        __syncthreads();
    }

    const int g  = lane >> 2, tg = lane & 3;
    #pragma unroll
    for (int mi = 0; mi < 4; mi++) {
        #pragma unroll
        for (int ns = 0; ns < 4; ns++) {
            int row = m0 + wm * 64 + mi * 16 + g;
            int col = n0 + wn * 32 + ns * 8 + tg * 2;
            float2 bb = *(const float2*)&bias[col];
            float2 v0 = {acc[mi][ns][0] + bb.x, acc[mi][ns][1] + bb.y};
            float2 v1 = {acc[mi][ns][2] + bb.x, acc[mi][ns][3] + bb.y};
            *(float2*)&C[(size_t)row * 512 + col]       = v0;
            *(float2*)&C[(size_t)(row + 8) * 512 + col] = v1;
        }
    }
}

// ---------------------------------------------------------------------------
// Flash attention: 256-query tiles (REVERTED to the proven round-7 kernel,
// 975us measured three times). One block per (256-query tile, head, batch).
// ---------------------------------------------------------------------------
__global__ __launch_bounds__(256) void attn_kernel(const int* __restrict__ mask)
{
    extern __shared__ float sm[];
    float* Qs   = sm;                    // [64][260]  Q k-major
    float* Ks   = Qs + 64 * 260;         // [64][68]   K k-major
    float* Vs   = Ks + 64 * 68;          // [64][68]   V s-major
    float* Ps   = Vs + 64 * 68;          // [64][260]  P s-major (swizzled cols)
    float* mneg = Ps + 64 * 260;         // [64]

    const int tid = threadIdx.x;
    const int tx = tid & 7;
    const int ty = tid >> 3;
    const int t0 = blockIdx.x * 256;
    const int h  = blockIdx.y;
    const int b  = blockIdx.z;

    #pragma unroll
    for (int r = 0; r < 16; r++) {
        int idx = tid + r * 256;
        int row = idx >> 4;
        int c4  = (idx & 15) * 4;
        float4 q = *(const float4*)&g_Q[((size_t)(b * Tv + t0 + row)) * HIDv + h * DKv + c4];
        Qs[(c4 + 0) * 260 + row] = q.x;
        Qs[(c4 + 1) * 260 + row] = q.y;
        Qs[(c4 + 2) * 260 + row] = q.z;
        Qs[(c4 + 3) * 260 + row] = q.w;
    }

    float rowM[8], rowL[8];
    #pragma unroll
    for (int i = 0; i < 8; i++) { rowM[i] = -1e30f; rowL[i] = 0.0f; }

    u64 acc2[8][4];
    #pragma unroll
    for (int i = 0; i < 8; i++)
        #pragma unroll
        for (int j = 0; j < 4; j++) acc2[i][j] = 0ull;

    const int Xst = (tx & 3) << 2;
    __syncthreads();

    for (int s0 = 0; s0 < Sv; s0 += 64) {
        #pragma unroll
        for (int r = 0; r < 4; r++) {
            int idx = tid + r * 256;
            int row = idx >> 4;
            int c4  = (idx & 15) * 4;
            size_t g = ((size_t)(b * Sv + s0 + row)) * HIDv + h * DKv + c4;
            float4 k = *(const float4*)&g_K[g];
            Ks[(c4 + 0) * 68 + row] = k.x;
            Ks[(c4 + 1) * 68 + row] = k.y;
            Ks[(c4 + 2) * 68 + row] = k.z;
            Ks[(c4 + 3) * 68 + row] = k.w;
            float4 v = *(const float4*)&g_V[g];
            *(float4*)&Vs[row * 68 + c4] = v;
        }
        if (tid < 64) mneg[tid] = (mask[b * Sv + s0 + tid] != 0) ? 0.0f : -1e20f;
        __syncthreads();

        u64 sc2[8][4];
        #pragma unroll
        for (int i = 0; i < 8; i++)
            #pragma unroll
            for (int j = 0; j < 4; j++) sc2[i][j] = 0ull;

        #pragma unroll 8
        for (int kk = 0; kk < 64; kk++) {
            float4 a0 = *(const float4*)&Qs[kk * 260 + ty * 8];
            float4 a1 = *(const float4*)&Qs[kk * 260 + ty * 8 + 4];
            ulonglong2 b0 = *(const ulonglong2*)&Ks[kk * 68 + tx * 8];
            ulonglong2 b1 = *(const ulonglong2*)&Ks[kk * 68 + tx * 8 + 4];
            u64 bb2[4] = {b0.x, b0.y, b1.x, b1.y};
            u64 a2[8];
            a2[0] = pdup(a0.x); a2[1] = pdup(a0.y);
            a2[2] = pdup(a0.z); a2[3] = pdup(a0.w);
            a2[4] = pdup(a1.x); a2[5] = pdup(a1.y);
            a2[6] = pdup(a1.z); a2[7] = pdup(a1.w);
            #pragma unroll
            for (int i = 0; i < 8; i++)
                #pragma unroll
                for (int j = 0; j < 4; j++)
                    sc2[i][j] = fma2(a2[i], bb2[j], sc2[i][j]);
        }

        {
            ulonglong2 m0 = *(const ulonglong2*)&mneg[tx * 8];
            ulonglong2 m1 = *(const ulonglong2*)&mneg[tx * 8 + 4];
            u64 mm[4] = {m0.x, m0.y, m1.x, m1.y};
            u64 c18 = pdup(0.125f);
            #pragma unroll
            for (int i = 0; i < 8; i++)
                #pragma unroll
                for (int j = 0; j < 4; j++)
                    sc2[i][j] = fma2(sc2[i][j], c18, mm[j]);
        }

        #pragma unroll
        for (int i = 0; i < 8; i++) {
            float s8[8];
            unpack2(sc2[i][0], s8[0], s8[1]);
            unpack2(sc2[i][1], s8[2], s8[3]);
            unpack2(sc2[i][2], s8[4], s8[5]);
            unpack2(sc2[i][3], s8[6], s8[7]);
            float mx = fmaxf(fmaxf(fmaxf(s8[0], s8[1]), fmaxf(s8[2], s8[3])),
                             fmaxf(fmaxf(s8[4], s8[5]), fmaxf(s8[6], s8[7])));
            #pragma unroll
            for (int o = 4; o >= 1; o >>= 1)
                mx = fmaxf(mx, __shfl_xor_sync(0xffffffffu, mx, o, 8));

            float mnw = fmaxf(rowM[i], mx);
            float f   = fast_exp(rowM[i] - mnw);
            rowM[i] = mnw;

            float p[8], se = 0.0f;
            #pragma unroll
            for (int k = 0; k < 8; k++) { p[k] = fast_exp(s8[k] - mnw); se += p[k]; }
            #pragma unroll
            for (int o = 4; o >= 1; o >>= 1)
                se += __shfl_xor_sync(0xffffffffu, se, o, 8);
            rowL[i] = rowL[i] * f + se;

            u64 f2 = pdup(f);
            #pragma unroll
            for (int j = 0; j < 4; j++) acc2[i][j] = mul2(acc2[i][j], f2);

            int colp = (ty * 8 + i) ^ Xst;
            #pragma unroll
            for (int j = 0; j < 8; j++)
                Ps[(tx * 8 + j) * 260 + colp] = p[j];
        }
        __syncthreads();

        #pragma unroll 2
        for (int g = 0; g < 8; g++) {
            const int X    = (g & 3) << 2;
            const int base = (ty * 8) ^ (X & 8);
            const int offA = base + (X & 4);
            const int offB = base + ((X & 4) ^ 4);
            #pragma unroll
            for (int js = 0; js < 8; js++) {
                int s = g * 8 + js;
                ulonglong2 pa = *(const ulonglong2*)&Ps[s * 260 + offA];
                ulonglong2 pb = *(const ulonglong2*)&Ps[s * 260 + offB];
                float p0, p1, p2v, p3, p4, p5, p6, p7;
                unpack2(pa.x, p0, p1); unpack2(pa.y, p2v, p3);
                unpack2(pb.x, p4, p5); unpack2(pb.y, p6, p7);
                u64 pp[8] = {pdup(p0), pdup(p1), pdup(p2v), pdup(p3),
                             pdup(p4), pdup(p5), pdup(p6),  pdup(p7)};
                ulonglong2 v0 = *(const ulonglong2*)&Vs[s * 68 + tx * 8];
                ulonglong2 v1 = *(const ulonglong2*)&Vs[s * 68 + tx * 8 + 4];
                u64 vv[4] = {v0.x, v0.y, v1.x, v1.y};
                #pragma unroll
                for (int i = 0; i < 8; i++)
                    #pragma unroll
                    for (int j = 0; j < 4; j++)
                        acc2[i][j] = fma2(pp[i], vv[j], acc2[i][j]);
            }
        }
        __syncthreads();
    }

    #pragma unroll
    for (int i = 0; i < 8; i++) {
        float inv = 1.0f / rowL[i];
        float o[8];
        unpack2(acc2[i][0], o[0], o[1]);
        unpack2(acc2[i][1], o[2], o[3]);
        unpack2(acc2[i][2], o[4], o[5]);
        unpack2(acc2[i][3], o[6], o[7]);
        float4 s0, s1;
        s0.x = o[0] * inv; s0.y = o[1] * inv; s0.z = o[2] * inv; s0.w = o[3] * inv;
        s1.x = o[4] * inv; s1.y = o[5] * inv; s1.z = o[6] * inv; s1.w = o[7] * inv;
        size_t base = ((size_t)(b * Tv + t0 + ty * 8 + i)) * HIDv + h * DKv + tx * 8;
        *(float4*)&g_ctx[base]     = s0;
        *(float4*)&g_ctx[base + 4] = s1;
    }
}

// ---------------------------------------------------------------------------

extern "C" void kernel_launch(void* const* d_in, const int* in_sizes, int n_in,
                              void* d_out, int out_size)
{
    const float* inputs  = (const float*)d_in[0];
    const float* targets = (const float*)d_in[1];
    const int*   mask    = (const int*)d_in[2];     // bool widened to int32
    const float* Wq = (const float*)d_in[3];
    const float* bq = (const float*)d_in[4];
    const float* Wk = (const float*)d_in[5];
    const float* bk = (const float*)d_in[6];
    const float* Wv = (const float*)d_in[7];
    const float* bv = (const float*)d_in[8];
    const float* Wo = (const float*)d_in[9];
    const float* bo = (const float*)d_in[10];
    float* out = (float*)d_out;

    float *pQ, *pK, *pV, *pC;
    cudaGetSymbolAddress((void**)&pQ, g_Q);
    cudaGetSymbolAddress((void**)&pK, g_K);
    cudaGetSymbolAddress((void**)&pV, g_V);
    cudaGetSymbolAddress((void**)&pC, g_ctx);
    __nv_bfloat16 *inH, *inL, *tgH, *tgL, *cxH, *cxL, *wH, *wL;
    cudaGetSymbolAddress((void**)&inH, g_in_hi);
    cudaGetSymbolAddress((void**)&inL, g_in_lo);
    cudaGetSymbolAddress((void**)&tgH, g_tg_hi);
    cudaGetSymbolAddress((void**)&tgL, g_tg_lo);
    cudaGetSymbolAddress((void**)&cxH, g_cx_hi);
    cudaGetSymbolAddress((void**)&cxL, g_cx_lo);
    cudaGetSymbolAddress((void**)&wH, g_w_hi);
    cudaGetSymbolAddress((void**)&wL, g_w_lo);

    const int ATTN_SMEM = (64 * 260 + 64 * 68 + 64 * 68 + 64 * 260 + 64) * (int)sizeof(float);
    cudaFuncSetAttribute(attn_kernel, cudaFuncAttributeMaxDynamicSharedMemorySize, ATTN_SMEM);
    cudaFuncSetAttribute(hmma_gemm, cudaFuncAttributeMaxDynamicSharedMemorySize, GSMEM);

    const int W_ELEMS = HIDv * HIDv;
    // ncu capture lands on the 4th kernel launch -> hmma K.
    cvt_kernel<<<(Bv * Sv * HIDv / 4 + 255) / 256, 256>>>(inputs, inH, inL, Bv * Sv * HIDv / 4);
    cvt_kernel<<<(W_ELEMS / 4 + 255) / 256, 256>>>(Wk, wH + 1 * W_ELEMS, wL + 1 * W_ELEMS, W_ELEMS / 4);
    cvt_kernel<<<(W_ELEMS / 4 + 255) / 256, 256>>>(Wv, wH + 2 * W_ELEMS, wL + 2 * W_ELEMS, W_ELEMS / 4);

    hmma_gemm<<<dim3(4, Bv * Sv / 128), 256, GSMEM>>>(inH, inL, wH + 1 * W_ELEMS, wL + 1 * W_ELEMS, bk, pK);  // 4th: captured
    hmma_gemm<<<dim3(4, Bv * Sv / 128), 256, GSMEM>>>(inH, inL, wH + 2 * W_ELEMS, wL + 2 * W_ELEMS, bv, pV);

    cvt_kernel<<<(Bv * Tv * HIDv / 4 + 255) / 256, 256>>>(targets, tgH, tgL, Bv * Tv * HIDv / 4);
    cvt_kernel<<<(W_ELEMS / 4 + 255) / 256, 256>>>(Wq, wH + 0 * W_ELEMS, wL + 0 * W_ELEMS, W_ELEMS / 4);
    hmma_gemm<<<dim3(4, Bv * Tv / 128), 256, GSMEM>>>(tgH, tgL, wH + 0 * W_ELEMS, wL + 0 * W_ELEMS, bq, pQ);

    attn_kernel<<<dim3(Tv / 256, HEADSv, Bv), 256, ATTN_SMEM>>>(mask);

    cvt_kernel<<<(Bv * Tv * HIDv / 4 + 255) / 256, 256>>>(pC, cxH, cxL, Bv * Tv * HIDv / 4);
    cvt_kernel<<<(W_ELEMS / 4 + 255) / 256, 256>>>(Wo, wH + 3 * W_ELEMS, wL + 3 * W_ELEMS, W_ELEMS / 4);
    hmma_gemm<<<dim3(4, Bv * Tv / 128), 256, GSMEM>>>(cxH, cxL, wH + 3 * W_ELEMS, wL + 3 * W_ELEMS, bo, out);
}

// round 16
// speedup vs baseline: 1.6370x; 1.2223x over previous
#include <cuda_runtime.h>
#include <cuda_bf16.h>
#include <math.h>

#define Bv    8
#define Sv    4096
#define Tv    512
#define HIDv  512
#define HEADSv 8
#define DKv   64

typedef unsigned long long u64;

// ------------------------- scratch (__device__ globals) --------------------
__device__ float g_ctx[Bv * Tv * HIDv];
__device__ __nv_bfloat16 g_in_hi[Bv * Sv * HIDv];
__device__ __nv_bfloat16 g_in_lo[Bv * Sv * HIDv];
__device__ __nv_bfloat16 g_tg_hi[Bv * Tv * HIDv];
__device__ __nv_bfloat16 g_tg_lo[Bv * Tv * HIDv];
__device__ __nv_bfloat16 g_cx_hi[Bv * Tv * HIDv];
__device__ __nv_bfloat16 g_cx_lo[Bv * Tv * HIDv];
__device__ __nv_bfloat16 g_w_hi[4 * HIDv * HIDv];
__device__ __nv_bfloat16 g_w_lo[4 * HIDv * HIDv];
// bf16 projection outputs
__device__ __nv_bfloat16 g_qh[Bv * Tv * HIDv];
__device__ __nv_bfloat16 g_ql[Bv * Tv * HIDv];
__device__ __nv_bfloat16 g_kh[Bv * Sv * HIDv];
__device__ __nv_bfloat16 g_kl[Bv * Sv * HIDv];
__device__ __nv_bfloat16 g_vh[Bv * Sv * HIDv];
__device__ __nv_bfloat16 g_vl[Bv * Sv * HIDv];

// ---------------- misc helpers --------------------------------------------
__device__ __forceinline__ float fast_exp(float x) {
    float y = fmaxf(x * 1.4426950408889634f, -126.0f);
    float n = rintf(y);
    float r = y - n;
    float q = 1.5403530394e-4f;
    q = fmaf(q, r, 1.3333558146e-3f);
    q = fmaf(q, r, 9.6181291076e-3f);
    q = fmaf(q, r, 5.5504108664e-2f);
    q = fmaf(q, r, 2.4022650696e-1f);
    q = fmaf(q, r, 6.9314718056e-1f);
    q = fmaf(q, r, 1.0f);
    return q * __int_as_float(((int)n + 127) << 23);
}
// pack (lo_elem, hi_elem) -> bf16x2 register (first PTX operand = HIGH half)
__device__ __forceinline__ unsigned packbf(float lo, float hi) {
    unsigned d;
    asm("cvt.rn.bf16x2.f32 %0, %1, %2;" : "=r"(d) : "f"(hi), "f"(lo));
    return d;
}

// ---------------- mma.sync + cp.async helpers (portable PTX) ---------------
__device__ __forceinline__ void ldm_x4(unsigned* r, unsigned saddr) {
    asm volatile("ldmatrix.sync.aligned.m8n8.x4.shared.b16 {%0,%1,%2,%3}, [%4];"
                 : "=r"(r[0]), "=r"(r[1]), "=r"(r[2]), "=r"(r[3]) : "r"(saddr));
}
__device__ __forceinline__ void ldm_x4_t(unsigned* r, unsigned saddr) {
    asm volatile("ldmatrix.sync.aligned.m8n8.x4.trans.shared.b16 {%0,%1,%2,%3}, [%4];"
                 : "=r"(r[0]), "=r"(r[1]), "=r"(r[2]), "=r"(r[3]) : "r"(saddr));
}
__device__ __forceinline__ void mma_bf16(float* d, const unsigned* a, const unsigned* b) {
    asm volatile(
        "mma.sync.aligned.m16n8k16.row.col.f32.bf16.bf16.f32 "
        "{%0,%1,%2,%3}, {%4,%5,%6,%7}, {%8,%9}, {%0,%1,%2,%3};"
        : "+f"(d[0]), "+f"(d[1]), "+f"(d[2]), "+f"(d[3])
        : "r"(a[0]), "r"(a[1]), "r"(a[2]), "r"(a[3]), "r"(b[0]), "r"(b[1]));
}
__device__ __forceinline__ void cp16(void* sdst, const void* gsrc) {
    unsigned s = (unsigned)__cvta_generic_to_shared(sdst);
    asm volatile("cp.async.ca.shared.global [%0], [%1], 16;" :: "r"(s), "l"(gsrc) : "memory");
}
__device__ __forceinline__ void cp_commit() {
    asm volatile("cp.async.commit_group;" ::: "memory");
}
template <int N> __device__ __forceinline__ void cp_wait() {
    asm volatile("cp.async.wait_group %0;" :: "n"(N) : "memory");
}

// ---------------------------------------------------------------------------
// fp32 -> (hi, lo) bf16 split, vectorized.
// ---------------------------------------------------------------------------
__global__ void cvt_kernel(const float* __restrict__ x,
                           __nv_bfloat16* __restrict__ hi,
                           __nv_bfloat16* __restrict__ lo, int n4)
{
    int i = blockIdx.x * blockDim.x + threadIdx.x;
    if (i >= n4) return;
    float4 v = ((const float4*)x)[i];
    __nv_bfloat16 h0 = __float2bfloat16(v.x);
    __nv_bfloat16 h1 = __float2bfloat16(v.y);
    __nv_bfloat16 h2 = __float2bfloat16(v.z);
    __nv_bfloat16 h3 = __float2bfloat16(v.w);
    __nv_bfloat16 l0 = __float2bfloat16(v.x - __bfloat162float(h0));
    __nv_bfloat16 l1 = __float2bfloat16(v.y - __bfloat162float(h1));
    __nv_bfloat16 l2 = __float2bfloat16(v.z - __bfloat162float(h2));
    __nv_bfloat16 l3 = __float2bfloat16(v.w - __bfloat162float(h3));
    ((__nv_bfloat162*)hi)[2 * i]     = __halves2bfloat162(h0, h1);
    ((__nv_bfloat162*)hi)[2 * i + 1] = __halves2bfloat162(h2, h3);
    ((__nv_bfloat162*)lo)[2 * i]     = __halves2bfloat162(l0, l1);
    ((__nv_bfloat162*)lo)[2 * i + 1] = __halves2bfloat162(l2, l3);
}

// ---------------------------------------------------------------------------
// HMMA GEMM mainloop (shared by both epilogues), 2-stage cp.async.
// ---------------------------------------------------------------------------
#define GP 72
#define STG_ELEMS (128 * GP)
#define STAGE_ELEMS (4 * STG_ELEMS)
#define GSMEM (2 * STAGE_ELEMS * 2)

#define HMMA_MAINLOOP(ACC)                                                           \
    const int tid  = threadIdx.x;                                                    \
    const int w    = tid >> 5, lane = tid & 31;                                      \
    const int wm   = w >> 2, wn = w & 3;                                             \
    const int m0   = blockIdx.y * 128;                                               \
    const int n0   = blockIdx.x * 128;                                               \
    const int aRow = wm * 64 + ((lane >> 3) & 1) * 8 + (lane & 7);                   \
    const int aK   = (lane >> 4) * 8;                                                \
    const int bRow = wn * 32 + (lane >> 4) * 8 + (lane & 7);                         \
    const int bK   = ((lane >> 3) & 1) * 8;                                          \
    auto issue = [&](int c, int st) {                                                \
        const int k0 = c * 64;                                                       \
        __nv_bfloat16* sA_hi = sb16 + st * STAGE_ELEMS;                              \
        __nv_bfloat16* sA_lo = sA_hi + STG_ELEMS;                                    \
        __nv_bfloat16* sW_hi = sA_lo + STG_ELEMS;                                    \
        __nv_bfloat16* sW_lo = sW_hi + STG_ELEMS;                                    \
        _Pragma("unroll")                                                            \
        for (int it = 0; it < 4; it++) {                                             \
            int idx = tid + it * 256;                                                \
            int row = idx >> 3;                                                      \
            int sg  = (idx & 7) * 8;                                                 \
            size_t ga = (size_t)(m0 + row) * 512 + k0 + sg;                          \
            size_t gw = (size_t)(n0 + row) * 512 + k0 + sg;                          \
            cp16(&sA_hi[row * GP + sg], &Ahi[ga]);                                   \
            cp16(&sA_lo[row * GP + sg], &Alo[ga]);                                   \
            cp16(&sW_hi[row * GP + sg], &Whi[gw]);                                   \
            cp16(&sW_lo[row * GP + sg], &Wlo[gw]);                                   \
        }                                                                            \
    };                                                                               \
    issue(0, 0);                                                                     \
    cp_commit();                                                                     \
    for (int c = 0; c < 8; c++) {                                                    \
        const int st = c & 1;                                                        \
        if (c < 7) { issue(c + 1, st ^ 1); cp_commit(); cp_wait<1>(); }              \
        else       { cp_wait<0>(); }                                                 \
        __syncthreads();                                                             \
        const unsigned uAhi = (unsigned)__cvta_generic_to_shared(sb16 + st * STAGE_ELEMS); \
        const unsigned uAlo = uAhi + STG_ELEMS * 2;                                  \
        const unsigned uWhi = uAlo + STG_ELEMS * 2;                                  \
        const unsigned uWlo = uWhi + STG_ELEMS * 2;                                  \
        _Pragma("unroll")                                                            \
        for (int ks = 0; ks < 4; ks++) {                                             \
            unsigned ah[4][4], bh[4][2], bl[4][2];                                   \
            _Pragma("unroll")                                                        \
            for (int mi = 0; mi < 4; mi++)                                           \
                ldm_x4(ah[mi], uAhi + (unsigned)(((aRow + mi * 16) * GP + ks * 16 + aK) * 2)); \
            _Pragma("unroll")                                                        \
            for (int pr = 0; pr < 2; pr++) {                                         \
                unsigned t[4];                                                       \
                ldm_x4(t, uWhi + (unsigned)(((bRow + pr * 16) * GP + ks * 16 + bK) * 2)); \
                bh[2 * pr][0] = t[0]; bh[2 * pr][1] = t[1];                          \
                bh[2 * pr + 1][0] = t[2]; bh[2 * pr + 1][1] = t[3];                  \
                ldm_x4(t, uWlo + (unsigned)(((bRow + pr * 16) * GP + ks * 16 + bK) * 2)); \
                bl[2 * pr][0] = t[0]; bl[2 * pr][1] = t[1];                          \
                bl[2 * pr + 1][0] = t[2]; bl[2 * pr + 1][1] = t[3];                  \
            }                                                                        \
            _Pragma("unroll")                                                        \
            for (int mi = 0; mi < 4; mi++)                                           \
                _Pragma("unroll")                                                    \
                for (int ns = 0; ns < 4; ns++) {                                     \
                    mma_bf16(ACC[mi][ns], ah[mi], bh[ns]);                           \
                    mma_bf16(ACC[mi][ns], ah[mi], bl[ns]);                           \
                }                                                                    \
            unsigned al[4][4];                                                       \
            _Pragma("unroll")                                                        \
            for (int mi = 0; mi < 4; mi++)                                           \
                ldm_x4(al[mi], uAlo + (unsigned)(((aRow + mi * 16) * GP + ks * 16 + aK) * 2)); \
            _Pragma("unroll")                                                        \
            for (int mi = 0; mi < 4; mi++)                                           \
                _Pragma("unroll")                                                    \
                for (int ns = 0; ns < 4; ns++)                                       \
                    mma_bf16(ACC[mi][ns], al[mi], bh[ns]);                           \
        }                                                                            \
        __syncthreads();                                                             \
    }

// fp32-output variant (used for the final O projection)
__global__ __launch_bounds__(256) void hmma_gemm(
    const __nv_bfloat16* __restrict__ Ahi, const __nv_bfloat16* __restrict__ Alo,
    const __nv_bfloat16* __restrict__ Whi, const __nv_bfloat16* __restrict__ Wlo,
    const float* __restrict__ bias, float* __restrict__ C)
{
    extern __shared__ __nv_bfloat16 sb16[];
    float acc[4][4][4];
    #pragma unroll
    for (int i = 0; i < 4; i++)
        #pragma unroll
        for (int j = 0; j < 4; j++)
            #pragma unroll
            for (int r = 0; r < 4; r++) acc[i][j][r] = 0.0f;
    HMMA_MAINLOOP(acc)
    const int g  = lane >> 2, tg = lane & 3;
    #pragma unroll
    for (int mi = 0; mi < 4; mi++) {
        #pragma unroll
        for (int ns = 0; ns < 4; ns++) {
            int row = m0 + wm * 64 + mi * 16 + g;
            int col = n0 + wn * 32 + ns * 8 + tg * 2;
            float2 bb = *(const float2*)&bias[col];
            float2 v0 = {acc[mi][ns][0] + bb.x, acc[mi][ns][1] + bb.y};
            float2 v1 = {acc[mi][ns][2] + bb.x, acc[mi][ns][3] + bb.y};
            *(float2*)&C[(size_t)row * 512 + col]       = v0;
            *(float2*)&C[(size_t)(row + 8) * 512 + col] = v1;
        }
    }
}

// bf16 hi/lo-output variant (Q/K/V projections feed the HMMA attention)
__global__ __launch_bounds__(256) void hmma_gemm_b16(
    const __nv_bfloat16* __restrict__ Ahi, const __nv_bfloat16* __restrict__ Alo,
    const __nv_bfloat16* __restrict__ Whi, const __nv_bfloat16* __restrict__ Wlo,
    const float* __restrict__ bias,
    __nv_bfloat16* __restrict__ Chi, __nv_bfloat16* __restrict__ Clo)
{
    extern __shared__ __nv_bfloat16 sb16[];
    float acc[4][4][4];
    #pragma unroll
    for (int i = 0; i < 4; i++)
        #pragma unroll
        for (int j = 0; j < 4; j++)
            #pragma unroll
            for (int r = 0; r < 4; r++) acc[i][j][r] = 0.0f;
    HMMA_MAINLOOP(acc)
    const int g  = lane >> 2, tg = lane & 3;
    #pragma unroll
    for (int mi = 0; mi < 4; mi++) {
        #pragma unroll
        for (int ns = 0; ns < 4; ns++) {
            int row = m0 + wm * 64 + mi * 16 + g;
            int col = n0 + wn * 32 + ns * 8 + tg * 2;
            float2 bb = *(const float2*)&bias[col];
            #pragma unroll
            for (int rr = 0; rr < 2; rr++) {
                float v0 = acc[mi][ns][rr * 2]     + bb.x;
                float v1 = acc[mi][ns][rr * 2 + 1] + bb.y;
                __nv_bfloat16 h0 = __float2bfloat16(v0);
                __nv_bfloat16 h1 = __float2bfloat16(v1);
                __nv_bfloat16 l0 = __float2bfloat16(v0 - __bfloat162float(h0));
                __nv_bfloat16 l1 = __float2bfloat16(v1 - __bfloat162float(h1));
                size_t o = (size_t)(row + rr * 8) * 512 + col;
                *(__nv_bfloat162*)&Chi[o] = __halves2bfloat162(h0, h1);
                *(__nv_bfloat162*)&Clo[o] = __halves2bfloat162(l0, l1);
            }
        }
    }
}

// ---------------------------------------------------------------------------
// HMMA flash attention. Grid (2, 8, 8); 256 thr = 8 warps; warp owns 32 q rows.
// QK^T: 3-term bf16 split. P·V: 3-term split (Phi·Vhi + Plo·Vhi + Phi·Vlo) —
// P AND V hi-only each inject ~2e-3 relative error into ctx (softmax mean
// does NOT average quantization noise down). P in registers end-to-end.
// ---------------------------------------------------------------------------
#define AP 72
#define ASMEM ((2 * 256 * AP + 4 * 2 * 64 * AP) * 2 + 4096 * 4)

__global__ __launch_bounds__(256) void attn_hmma(
    const int* __restrict__ mask,
    const __nv_bfloat16* __restrict__ qh, const __nv_bfloat16* __restrict__ ql,
    const __nv_bfloat16* __restrict__ kh, const __nv_bfloat16* __restrict__ kl,
    const __nv_bfloat16* __restrict__ vh, const __nv_bfloat16* __restrict__ vl)
{
    extern __shared__ __nv_bfloat16 sb16[];
    __nv_bfloat16* sQh = sb16;                    // [256][AP]
    __nv_bfloat16* sQl = sQh + 256 * AP;
    __nv_bfloat16* sKh = sQl + 256 * AP;          // [2][64][AP]
    __nv_bfloat16* sKl = sKh + 2 * 64 * AP;
    __nv_bfloat16* sVh = sKl + 2 * 64 * AP;       // [2][64][AP]
    __nv_bfloat16* sVl = sVh + 2 * 64 * AP;       // [2][64][AP]
    float* mnegAll = (float*)(sVl + 2 * 64 * AP); // [4096]

    const int tid = threadIdx.x, w = tid >> 5, lane = tid & 31;
    const int g = lane >> 2, tg = lane & 3;
    const int t0 = blockIdx.x * 256;
    const int h  = blockIdx.y;
    const int b  = blockIdx.z;

    for (int i = tid; i < Sv; i += 256)
        mnegAll[i] = (mask[b * Sv + i] != 0) ? 0.0f : -1e20f;

    #pragma unroll
    for (int it = 0; it < 8; it++) {
        int idx = tid + it * 256;
        int row = idx >> 3, sg = (idx & 7) * 8;
        size_t gq = (size_t)(b * Tv + t0 + row) * 512 + h * DKv + sg;
        *(uint4*)&sQh[row * AP + sg] = *(const uint4*)&qh[gq];
        *(uint4*)&sQl[row * AP + sg] = *(const uint4*)&ql[gq];
    }

    auto issueKV = [&](int c, int st) {
        int s0 = c * 64;
        #pragma unroll
        for (int it = 0; it < 2; it++) {
            int idx = tid + it * 256;
            int row = idx >> 3, sg = (idx & 7) * 8;
            size_t gk = (size_t)(b * Sv + s0 + row) * 512 + h * DKv + sg;
            cp16(&sKh[(st * 64 + row) * AP + sg], &kh[gk]);
            cp16(&sKl[(st * 64 + row) * AP + sg], &kl[gk]);
            cp16(&sVh[(st * 64 + row) * AP + sg], &vh[gk]);
            cp16(&sVl[(st * 64 + row) * AP + sg], &vl[gk]);
        }
    };

    const int aRow = w * 32 + ((lane >> 3) & 1) * 8 + (lane & 7);
    const int aK   = (lane >> 4) * 8;
    const int bRow = (lane >> 4) * 8 + (lane & 7);
    const int bK   = ((lane >> 3) & 1) * 8;
    const int vR   = (lane & 7) + ((lane >> 3) & 1) * 8;
    const int vC   = (lane >> 4) * 8;

    float o_acc[2][8][4];
    #pragma unroll
    for (int mi = 0; mi < 2; mi++)
        #pragma unroll
        for (int nd = 0; nd < 8; nd++)
            #pragma unroll
            for (int r = 0; r < 4; r++) o_acc[mi][nd][r] = 0.0f;
    float rowM[4], rowL[4];
    #pragma unroll
    for (int r = 0; r < 4; r++) { rowM[r] = -1e30f; rowL[r] = 0.0f; }

    issueKV(0, 0);
    cp_commit();

    const unsigned uQh = (unsigned)__cvta_generic_to_shared(sQh);
    const unsigned uQl = uQh + 256 * AP * 2;

    for (int c = 0; c < 64; c++) {
        const int st = c & 1;
        if (c < 63) { issueKV(c + 1, st ^ 1); cp_commit(); cp_wait<1>(); }
        else        { cp_wait<0>(); }
        __syncthreads();

        const unsigned uKh = (unsigned)__cvta_generic_to_shared(sKh + st * 64 * AP);
        const unsigned uKl = (unsigned)__cvta_generic_to_shared(sKl + st * 64 * AP);
        const unsigned uVh = (unsigned)__cvta_generic_to_shared(sVh + st * 64 * AP);
        const unsigned uVl = (unsigned)__cvta_generic_to_shared(sVl + st * 64 * AP);

        // ---- QK^T (3-term) ----
        float sc[2][8][4];
        #pragma unroll
        for (int mi = 0; mi < 2; mi++)
            #pragma unroll
            for (int ns = 0; ns < 8; ns++)
                #pragma unroll
                for (int r = 0; r < 4; r++) sc[mi][ns][r] = 0.0f;

        #pragma unroll
        for (int ks = 0; ks < 4; ks++) {
            unsigned ah[2][4], al[2][4];
            #pragma unroll
            for (int mi = 0; mi < 2; mi++) {
                ldm_x4(ah[mi], uQh + (unsigned)(((aRow + mi * 16) * AP + ks * 16 + aK) * 2));
                ldm_x4(al[mi], uQl + (unsigned)(((aRow + mi * 16) * AP + ks * 16 + aK) * 2));
            }
            #pragma unroll
            for (int pr = 0; pr < 4; pr++) {
                unsigned th[4], tl[4];
                ldm_x4(th, uKh + (unsigned)(((bRow + pr * 16) * AP + ks * 16 + bK) * 2));
                ldm_x4(tl, uKl + (unsigned)(((bRow + pr * 16) * AP + ks * 16 + bK) * 2));
                #pragma unroll
                for (int mi = 0; mi < 2; mi++) {
                    mma_bf16(sc[mi][2 * pr],     ah[mi], th);
                    mma_bf16(sc[mi][2 * pr + 1], ah[mi], th + 2);
                    mma_bf16(sc[mi][2 * pr],     ah[mi], tl);
                    mma_bf16(sc[mi][2 * pr + 1], ah[mi], tl + 2);
                    mma_bf16(sc[mi][2 * pr],     al[mi], th);
                    mma_bf16(sc[mi][2 * pr + 1], al[mi], th + 2);
                }
            }
        }

        // ---- scale + mask ----
        const int s0 = c * 64;
        #pragma unroll
        for (int ns = 0; ns < 8; ns++) {
            float2 mv = *(const float2*)&mnegAll[s0 + ns * 8 + tg * 2];
            #pragma unroll
            for (int mi = 0; mi < 2; mi++) {
                sc[mi][ns][0] = fmaf(sc[mi][ns][0], 0.125f, mv.x);
                sc[mi][ns][1] = fmaf(sc[mi][ns][1], 0.125f, mv.y);
                sc[mi][ns][2] = fmaf(sc[mi][ns][2], 0.125f, mv.x);
                sc[mi][ns][3] = fmaf(sc[mi][ns][3], 0.125f, mv.y);
            }
        }

        // ---- online softmax ----
        #pragma unroll
        for (int mi = 0; mi < 2; mi++) {
            #pragma unroll
            for (int hf = 0; hf < 2; hf++) {
                int r = mi * 2 + hf;
                float mx = -1e30f;
                #pragma unroll
                for (int ns = 0; ns < 8; ns++)
                    mx = fmaxf(mx, fmaxf(sc[mi][ns][hf * 2], sc[mi][ns][hf * 2 + 1]));
                mx = fmaxf(mx, __shfl_xor_sync(0xffffffffu, mx, 1, 4));
                mx = fmaxf(mx, __shfl_xor_sync(0xffffffffu, mx, 2, 4));
                float mnw = fmaxf(rowM[r], mx);
                float f = fast_exp(rowM[r] - mnw);
                rowM[r] = mnw;
                float se = 0.0f;
                #pragma unroll
                for (int ns = 0; ns < 8; ns++) {
                    float p0 = fast_exp(sc[mi][ns][hf * 2]     - mnw);
                    float p1 = fast_exp(sc[mi][ns][hf * 2 + 1] - mnw);
                    sc[mi][ns][hf * 2] = p0; sc[mi][ns][hf * 2 + 1] = p1;
                    se += p0 + p1;
                }
                se += __shfl_xor_sync(0xffffffffu, se, 1, 4);
                se += __shfl_xor_sync(0xffffffffu, se, 2, 4);
                rowL[r] = rowL[r] * f + se;
                #pragma unroll
                for (int nd = 0; nd < 8; nd++) {
                    o_acc[mi][nd][hf * 2]     *= f;
                    o_acc[mi][nd][hf * 2 + 1] *= f;
                }
            }
        }

        // ---- P @ V (3-term): P split in regs, V hi+lo from smem ----
        #pragma unroll
        for (int kp = 0; kp < 4; kp++) {
            unsigned pah[2][4], pal[2][4];
            #pragma unroll
            for (int mi = 0; mi < 2; mi++) {
                #pragma unroll
                for (int q = 0; q < 4; q++) {
                    float c0 = sc[mi][2 * kp + (q >> 1)][(q & 1) * 1 + ((q >> 1) ? 0 : 0) + ((q & 2) ? 0 : 0)];
                    (void)c0;
                }
                // explicit mapping (regs 0..3 of A-frag):
                float e0 = sc[mi][2 * kp][0],     e1 = sc[mi][2 * kp][1];
                float e2 = sc[mi][2 * kp][2],     e3 = sc[mi][2 * kp][3];
                float e4 = sc[mi][2 * kp + 1][0], e5 = sc[mi][2 * kp + 1][1];
                float e6 = sc[mi][2 * kp + 1][2], e7 = sc[mi][2 * kp + 1][3];
                unsigned h0 = packbf(e0, e1), h1 = packbf(e2, e3);
                unsigned h2 = packbf(e4, e5), h3 = packbf(e6, e7);
                pah[mi][0] = h0; pah[mi][1] = h1; pah[mi][2] = h2; pah[mi][3] = h3;
                pal[mi][0] = packbf(e0 - __uint_as_float(h0 << 16),
                                    e1 - __uint_as_float(h0 & 0xffff0000u));
                pal[mi][1] = packbf(e2 - __uint_as_float(h1 << 16),
                                    e3 - __uint_as_float(h1 & 0xffff0000u));
                pal[mi][2] = packbf(e4 - __uint_as_float(h2 << 16),
                                    e5 - __uint_as_float(h2 & 0xffff0000u));
                pal[mi][3] = packbf(e6 - __uint_as_float(h3 << 16),
                                    e7 - __uint_as_float(h3 & 0xffff0000u));
            }
            #pragma unroll
            for (int np = 0; np < 4; np++) {
                unsigned th[4], tl[4];
                ldm_x4_t(th, uVh + (unsigned)(((kp * 16 + vR) * AP + np * 16 + vC) * 2));
                ldm_x4_t(tl, uVl + (unsigned)(((kp * 16 + vR) * AP + np * 16 + vC) * 2));
                #pragma unroll
                for (int mi = 0; mi < 2; mi++) {
                    mma_bf16(o_acc[mi][2 * np],     pah[mi], th);      // Phi*Vhi
                    mma_bf16(o_acc[mi][2 * np + 1], pah[mi], th + 2);
                    mma_bf16(o_acc[mi][2 * np],     pal[mi], th);      // Plo*Vhi
                    mma_bf16(o_acc[mi][2 * np + 1], pal[mi], th + 2);
                    mma_bf16(o_acc[mi][2 * np],     pah[mi], tl);      // Phi*Vlo
                    mma_bf16(o_acc[mi][2 * np + 1], pah[mi], tl + 2);
                }
            }
        }
        __syncthreads();
    }

    // ---- normalize + write ctx ----
    #pragma unroll
    for (int mi = 0; mi < 2; mi++) {
        float inv0 = 1.0f / rowL[mi * 2];
        float inv1 = 1.0f / rowL[mi * 2 + 1];
        int row = t0 + w * 32 + mi * 16 + g;
        #pragma unroll
        for (int nd = 0; nd < 8; nd++) {
            int col = h * DKv + nd * 8 + tg * 2;
            float2 v0 = {o_acc[mi][nd][0] * inv0, o_acc[mi][nd][1] * inv0};
            float2 v1 = {o_acc[mi][nd][2] * inv1, o_acc[mi][nd][3] * inv1};
            *(float2*)&g_ctx[(size_t)(b * Tv + row) * 512 + col]     = v0;
            *(float2*)&g_ctx[(size_t)(b * Tv + row + 8) * 512 + col] = v1;
        }
    }
}

// ---------------------------------------------------------------------------

extern "C" void kernel_launch(void* const* d_in, const int* in_sizes, int n_in,
                              void* d_out, int out_size)
{
    const float* inputs  = (const float*)d_in[0];
    const float* targets = (const float*)d_in[1];
    const int*   mask    = (const int*)d_in[2];     // bool widened to int32
    const float* Wq = (const float*)d_in[3];
    const float* bq = (const float*)d_in[4];
    const float* Wk = (const float*)d_in[5];
    const float* bk = (const float*)d_in[6];
    const float* Wv = (const float*)d_in[7];
    const float* bv = (const float*)d_in[8];
    const float* Wo = (const float*)d_in[9];
    const float* bo = (const float*)d_in[10];
    float* out = (float*)d_out;

    float* pC;
    cudaGetSymbolAddress((void**)&pC, g_ctx);
    __nv_bfloat16 *inH, *inL, *tgH, *tgL, *cxH, *cxL, *wH, *wL;
    __nv_bfloat16 *qH, *qL, *kH, *kL, *vH, *vL;
    cudaGetSymbolAddress((void**)&inH, g_in_hi);
    cudaGetSymbolAddress((void**)&inL, g_in_lo);
    cudaGetSymbolAddress((void**)&tgH, g_tg_hi);
    cudaGetSymbolAddress((void**)&tgL, g_tg_lo);
    cudaGetSymbolAddress((void**)&cxH, g_cx_hi);
    cudaGetSymbolAddress((void**)&cxL, g_cx_lo);
    cudaGetSymbolAddress((void**)&wH, g_w_hi);
    cudaGetSymbolAddress((void**)&wL, g_w_lo);
    cudaGetSymbolAddress((void**)&qH, g_qh);
    cudaGetSymbolAddress((void**)&qL, g_ql);
    cudaGetSymbolAddress((void**)&kH, g_kh);
    cudaGetSymbolAddress((void**)&kL, g_kl);
    cudaGetSymbolAddress((void**)&vH, g_vh);
    cudaGetSymbolAddress((void**)&vL, g_vl);

    cudaFuncSetAttribute(hmma_gemm, cudaFuncAttributeMaxDynamicSharedMemorySize, GSMEM);
    cudaFuncSetAttribute(hmma_gemm_b16, cudaFuncAttributeMaxDynamicSharedMemorySize, GSMEM);
    cudaFuncSetAttribute(attn_hmma, cudaFuncAttributeMaxDynamicSharedMemorySize, ASMEM);

    const int W_ELEMS = HIDv * HIDv;
    // ncu capture = 4th launch -> hmma_gemm_b16 K.
    cvt_kernel<<<(Bv * Sv * HIDv / 4 + 255) / 256, 256>>>(inputs, inH, inL, Bv * Sv * HIDv / 4);
    cvt_kernel<<<(W_ELEMS / 4 + 255) / 256, 256>>>(Wk, wH + 1 * W_ELEMS, wL + 1 * W_ELEMS, W_ELEMS / 4);
    cvt_kernel<<<(W_ELEMS / 4 + 255) / 256, 256>>>(Wv, wH + 2 * W_ELEMS, wL + 2 * W_ELEMS, W_ELEMS / 4);

    hmma_gemm_b16<<<dim3(4, Bv * Sv / 128), 256, GSMEM>>>(inH, inL, wH + 1 * W_ELEMS, wL + 1 * W_ELEMS, bk, kH, kL);
    hmma_gemm_b16<<<dim3(4, Bv * Sv / 128), 256, GSMEM>>>(inH, inL, wH + 2 * W_ELEMS, wL + 2 * W_ELEMS, bv, vH, vL);

    cvt_kernel<<<(Bv * Tv * HIDv / 4 + 255) / 256, 256>>>(targets, tgH, tgL, Bv * Tv * HIDv / 4);
    cvt_kernel<<<(W_ELEMS / 4 + 255) / 256, 256>>>(Wq, wH + 0 * W_ELEMS, wL + 0 * W_ELEMS, W_ELEMS / 4);
    hmma_gemm_b16<<<dim3(4, Bv * Tv / 128), 256, GSMEM>>>(tgH, tgL, wH + 0 * W_ELEMS, wL + 0 * W_ELEMS, bq, qH, qL);

    attn_hmma<<<dim3(Tv / 256, HEADSv, Bv), 256, ASMEM>>>(mask, qH, qL, kH, kL, vH, vL);

    cvt_kernel<<<(Bv * Tv * HIDv / 4 + 255) / 256, 256>>>(pC, cxH, cxL, Bv * Tv * HIDv / 4);
    cvt_kernel<<<(W_ELEMS / 4 + 255) / 256, 256>>>(Wo, wH + 3 * W_ELEMS, wL + 3 * W_ELEMS, W_ELEMS / 4);
    hmma_gemm<<<dim3(4, Bv * Tv / 128), 256, GSMEM>>>(cxH, cxL, wH + 3 * W_ELEMS, wL + 3 * W_ELEMS, bo, out);
}

// round 17
// speedup vs baseline: 2.7297x; 1.6675x over previous
#include <cuda_runtime.h>
#include <cuda_bf16.h>
#include <math.h>

#define Bv    8
#define Sv    4096
#define Tv    512
#define HIDv  512
#define HEADSv 8
#define DKv   64

typedef unsigned long long u64;

// ------------------------- scratch (__device__ globals) --------------------
__device__ float g_ctx[Bv * Tv * HIDv];
__device__ __nv_bfloat16 g_in_hi[Bv * Sv * HIDv];
__device__ __nv_bfloat16 g_in_lo[Bv * Sv * HIDv];
__device__ __nv_bfloat16 g_tg_hi[Bv * Tv * HIDv];
__device__ __nv_bfloat16 g_tg_lo[Bv * Tv * HIDv];
__device__ __nv_bfloat16 g_cx_hi[Bv * Tv * HIDv];
__device__ __nv_bfloat16 g_cx_lo[Bv * Tv * HIDv];
__device__ __nv_bfloat16 g_w_hi[4 * HIDv * HIDv];
__device__ __nv_bfloat16 g_w_lo[4 * HIDv * HIDv];
// bf16 projection outputs
__device__ __nv_bfloat16 g_qh[Bv * Tv * HIDv];
__device__ __nv_bfloat16 g_ql[Bv * Tv * HIDv];
__device__ __nv_bfloat16 g_kh[Bv * Sv * HIDv];
__device__ __nv_bfloat16 g_kl[Bv * Sv * HIDv];
__device__ __nv_bfloat16 g_vh[Bv * Sv * HIDv];
__device__ __nv_bfloat16 g_vl[Bv * Sv * HIDv];

// ---------------- misc helpers --------------------------------------------
__device__ __forceinline__ float fast_exp(float x) {
    float y = fmaxf(x * 1.4426950408889634f, -126.0f);
    float n = rintf(y);
    float r = y - n;
    float q = 1.5403530394e-4f;
    q = fmaf(q, r, 1.3333558146e-3f);
    q = fmaf(q, r, 9.6181291076e-3f);
    q = fmaf(q, r, 5.5504108664e-2f);
    q = fmaf(q, r, 2.4022650696e-1f);
    q = fmaf(q, r, 6.9314718056e-1f);
    q = fmaf(q, r, 1.0f);
    return q * __int_as_float(((int)n + 127) << 23);
}
// pack (lo_elem, hi_elem) -> bf16x2 register (first PTX operand = HIGH half)
__device__ __forceinline__ unsigned packbf(float lo, float hi) {
    unsigned d;
    asm("cvt.rn.bf16x2.f32 %0, %1, %2;" : "=r"(d) : "f"(hi), "f"(lo));
    return d;
}

// ---------------- mma.sync + cp.async helpers (portable PTX) ---------------
__device__ __forceinline__ void ldm_x4(unsigned* r, unsigned saddr) {
    asm volatile("ldmatrix.sync.aligned.m8n8.x4.shared.b16 {%0,%1,%2,%3}, [%4];"
                 : "=r"(r[0]), "=r"(r[1]), "=r"(r[2]), "=r"(r[3]) : "r"(saddr));
}
__device__ __forceinline__ void ldm_x4_t(unsigned* r, unsigned saddr) {
    asm volatile("ldmatrix.sync.aligned.m8n8.x4.trans.shared.b16 {%0,%1,%2,%3}, [%4];"
                 : "=r"(r[0]), "=r"(r[1]), "=r"(r[2]), "=r"(r[3]) : "r"(saddr));
}
__device__ __forceinline__ void mma_bf16(float* d, const unsigned* a, const unsigned* b) {
    asm volatile(
        "mma.sync.aligned.m16n8k16.row.col.f32.bf16.bf16.f32 "
        "{%0,%1,%2,%3}, {%4,%5,%6,%7}, {%8,%9}, {%0,%1,%2,%3};"
        : "+f"(d[0]), "+f"(d[1]), "+f"(d[2]), "+f"(d[3])
        : "r"(a[0]), "r"(a[1]), "r"(a[2]), "r"(a[3]), "r"(b[0]), "r"(b[1]));
}
__device__ __forceinline__ void cp16(void* sdst, const void* gsrc) {
    unsigned s = (unsigned)__cvta_generic_to_shared(sdst);
    asm volatile("cp.async.ca.shared.global [%0], [%1], 16;" :: "r"(s), "l"(gsrc) : "memory");
}
__device__ __forceinline__ void cp_commit() {
    asm volatile("cp.async.commit_group;" ::: "memory");
}
template <int N> __device__ __forceinline__ void cp_wait() {
    asm volatile("cp.async.wait_group %0;" :: "n"(N) : "memory");
}

// ---------------------------------------------------------------------------
// fp32 -> (hi, lo) bf16 split, vectorized.
// ---------------------------------------------------------------------------
__global__ void cvt_kernel(const float* __restrict__ x,
                           __nv_bfloat16* __restrict__ hi,
                           __nv_bfloat16* __restrict__ lo, int n4)
{
    int i = blockIdx.x * blockDim.x + threadIdx.x;
    if (i >= n4) return;
    float4 v = ((const float4*)x)[i];
    __nv_bfloat16 h0 = __float2bfloat16(v.x);
    __nv_bfloat16 h1 = __float2bfloat16(v.y);
    __nv_bfloat16 h2 = __float2bfloat16(v.z);
    __nv_bfloat16 h3 = __float2bfloat16(v.w);
    __nv_bfloat16 l0 = __float2bfloat16(v.x - __bfloat162float(h0));
    __nv_bfloat16 l1 = __float2bfloat16(v.y - __bfloat162float(h1));
    __nv_bfloat16 l2 = __float2bfloat16(v.z - __bfloat162float(h2));
    __nv_bfloat16 l3 = __float2bfloat16(v.w - __bfloat162float(h3));
    ((__nv_bfloat162*)hi)[2 * i]     = __halves2bfloat162(h0, h1);
    ((__nv_bfloat162*)hi)[2 * i + 1] = __halves2bfloat162(h2, h3);
    ((__nv_bfloat162*)lo)[2 * i]     = __halves2bfloat162(l0, l1);
    ((__nv_bfloat162*)lo)[2 * i + 1] = __halves2bfloat162(l2, l3);
}

// ---------------------------------------------------------------------------
// HMMA GEMM mainloop (shared by both epilogues), 2-stage cp.async.
// ---------------------------------------------------------------------------
#define GP 72
#define STG_ELEMS (128 * GP)
#define STAGE_ELEMS (4 * STG_ELEMS)
#define GSMEM (2 * STAGE_ELEMS * 2)

#define HMMA_MAINLOOP(ACC)                                                           \
    const int tid  = threadIdx.x;                                                    \
    const int w    = tid >> 5, lane = tid & 31;                                      \
    const int wm   = w >> 2, wn = w & 3;                                             \
    const int m0   = blockIdx.y * 128;                                               \
    const int n0   = blockIdx.x * 128;                                               \
    const int aRow = wm * 64 + ((lane >> 3) & 1) * 8 + (lane & 7);                   \
    const int aK   = (lane >> 4) * 8;                                                \
    const int bRow = wn * 32 + (lane >> 4) * 8 + (lane & 7);                         \
    const int bK   = ((lane >> 3) & 1) * 8;                                          \
    auto issue = [&](int c, int st) {                                                \
        const int k0 = c * 64;                                                       \
        __nv_bfloat16* sA_hi = sb16 + st * STAGE_ELEMS;                              \
        __nv_bfloat16* sA_lo = sA_hi + STG_ELEMS;                                    \
        __nv_bfloat16* sW_hi = sA_lo + STG_ELEMS;                                    \
        __nv_bfloat16* sW_lo = sW_hi + STG_ELEMS;                                    \
        _Pragma("unroll")                                                            \
        for (int it = 0; it < 4; it++) {                                             \
            int idx = tid + it * 256;                                                \
            int row = idx >> 3;                                                      \
            int sg  = (idx & 7) * 8;                                                 \
            size_t ga = (size_t)(m0 + row) * 512 + k0 + sg;                          \
            size_t gw = (size_t)(n0 + row) * 512 + k0 + sg;                          \
            cp16(&sA_hi[row * GP + sg], &Ahi[ga]);                                   \
            cp16(&sA_lo[row * GP + sg], &Alo[ga]);                                   \
            cp16(&sW_hi[row * GP + sg], &Whi[gw]);                                   \
            cp16(&sW_lo[row * GP + sg], &Wlo[gw]);                                   \
        }                                                                            \
    };                                                                               \
    issue(0, 0);                                                                     \
    cp_commit();                                                                     \
    for (int c = 0; c < 8; c++) {                                                    \
        const int st = c & 1;                                                        \
        if (c < 7) { issue(c + 1, st ^ 1); cp_commit(); cp_wait<1>(); }              \
        else       { cp_wait<0>(); }                                                 \
        __syncthreads();                                                             \
        const unsigned uAhi = (unsigned)__cvta_generic_to_shared(sb16 + st * STAGE_ELEMS); \
        const unsigned uAlo = uAhi + STG_ELEMS * 2;                                  \
        const unsigned uWhi = uAlo + STG_ELEMS * 2;                                  \
        const unsigned uWlo = uWhi + STG_ELEMS * 2;                                  \
        _Pragma("unroll")                                                            \
        for (int ks = 0; ks < 4; ks++) {                                             \
            unsigned ah[4][4], bh[4][2], bl[4][2];                                   \
            _Pragma("unroll")                                                        \
            for (int mi = 0; mi < 4; mi++)                                           \
                ldm_x4(ah[mi], uAhi + (unsigned)(((aRow + mi * 16) * GP + ks * 16 + aK) * 2)); \
            _Pragma("unroll")                                                        \
            for (int pr = 0; pr < 2; pr++) {                                         \
                unsigned t[4];                                                       \
                ldm_x4(t, uWhi + (unsigned)(((bRow + pr * 16) * GP + ks * 16 + bK) * 2)); \
                bh[2 * pr][0] = t[0]; bh[2 * pr][1] = t[1];                          \
                bh[2 * pr + 1][0] = t[2]; bh[2 * pr + 1][1] = t[3];                  \
                ldm_x4(t, uWlo + (unsigned)(((bRow + pr * 16) * GP + ks * 16 + bK) * 2)); \
                bl[2 * pr][0] = t[0]; bl[2 * pr][1] = t[1];                          \
                bl[2 * pr + 1][0] = t[2]; bl[2 * pr + 1][1] = t[3];                  \
            }                                                                        \
            _Pragma("unroll")                                                        \
            for (int mi = 0; mi < 4; mi++)                                           \
                _Pragma("unroll")                                                    \
                for (int ns = 0; ns < 4; ns++) {                                     \
                    mma_bf16(ACC[mi][ns], ah[mi], bh[ns]);                           \
                    mma_bf16(ACC[mi][ns], ah[mi], bl[ns]);                           \
                }                                                                    \
            unsigned al[4][4];                                                       \
            _Pragma("unroll")                                                        \
            for (int mi = 0; mi < 4; mi++)                                           \
                ldm_x4(al[mi], uAlo + (unsigned)(((aRow + mi * 16) * GP + ks * 16 + aK) * 2)); \
            _Pragma("unroll")                                                        \
            for (int mi = 0; mi < 4; mi++)                                           \
                _Pragma("unroll")                                                    \
                for (int ns = 0; ns < 4; ns++)                                       \
                    mma_bf16(ACC[mi][ns], al[mi], bh[ns]);                           \
        }                                                                            \
        __syncthreads();                                                             \
    }

// fp32-output variant (used for the final O projection)
__global__ __launch_bounds__(256) void hmma_gemm(
    const __nv_bfloat16* __restrict__ Ahi, const __nv_bfloat16* __restrict__ Alo,
    const __nv_bfloat16* __restrict__ Whi, const __nv_bfloat16* __restrict__ Wlo,
    const float* __restrict__ bias, float* __restrict__ C)
{
    extern __shared__ __nv_bfloat16 sb16[];
    float acc[4][4][4];
    #pragma unroll
    for (int i = 0; i < 4; i++)
        #pragma unroll
        for (int j = 0; j < 4; j++)
            #pragma unroll
            for (int r = 0; r < 4; r++) acc[i][j][r] = 0.0f;
    HMMA_MAINLOOP(acc)
    const int g  = lane >> 2, tg = lane & 3;
    #pragma unroll
    for (int mi = 0; mi < 4; mi++) {
        #pragma unroll
        for (int ns = 0; ns < 4; ns++) {
            int row = m0 + wm * 64 + mi * 16 + g;
            int col = n0 + wn * 32 + ns * 8 + tg * 2;
            float2 bb = *(const float2*)&bias[col];
            float2 v0 = {acc[mi][ns][0] + bb.x, acc[mi][ns][1] + bb.y};
            float2 v1 = {acc[mi][ns][2] + bb.x, acc[mi][ns][3] + bb.y};
            *(float2*)&C[(size_t)row * 512 + col]       = v0;
            *(float2*)&C[(size_t)(row + 8) * 512 + col] = v1;
        }
    }
}

// bf16 hi/lo-output variant (Q/K/V projections feed the HMMA attention).
// Epilogue stages acc through smem (fp32 [128][132]) so the global stores are
// fully coalesced 8B writes: the direct fragment epilogue's scattered 4B STGs
// inflate L2 sector traffic ~8x and cost ~95us on the 32768-row gemms.
__global__ __launch_bounds__(256) void hmma_gemm_b16(
    const __nv_bfloat16* __restrict__ Ahi, const __nv_bfloat16* __restrict__ Alo,
    const __nv_bfloat16* __restrict__ Whi, const __nv_bfloat16* __restrict__ Wlo,
    const float* __restrict__ bias,
    __nv_bfloat16* __restrict__ Chi, __nv_bfloat16* __restrict__ Clo)
{
    extern __shared__ __nv_bfloat16 sb16[];
    float acc[4][4][4];
    #pragma unroll
    for (int i = 0; i < 4; i++)
        #pragma unroll
        for (int j = 0; j < 4; j++)
            #pragma unroll
            for (int r = 0; r < 4; r++) acc[i][j][r] = 0.0f;
    HMMA_MAINLOOP(acc)

    // Stage 1: fragments + bias -> smem fp32 [128][132]   (67.6 KB, fits)
    const int g  = lane >> 2, tg = lane & 3;
    float* sOut = (float*)sb16;
    const int OP = 132;
    #pragma unroll
    for (int mi = 0; mi < 4; mi++) {
        #pragma unroll
        for (int ns = 0; ns < 4; ns++) {
            int row = wm * 64 + mi * 16 + g;
            int col = wn * 32 + ns * 8 + tg * 2;
            float2 bb = *(const float2*)&bias[n0 + col];
            float2 v0 = {acc[mi][ns][0] + bb.x, acc[mi][ns][1] + bb.y};
            float2 v1 = {acc[mi][ns][2] + bb.x, acc[mi][ns][3] + bb.y};
            *(float2*)&sOut[row * OP + col]       = v0;
            *(float2*)&sOut[(row + 8) * OP + col] = v1;
        }
    }
    __syncthreads();

    // Stage 2: cooperative coalesced split-store (8B per array per thread-iter)
    #pragma unroll
    for (int it = 0; it < 16; it++) {
        int idx = tid + it * 256;            // 0..4095 float4 slots
        int row = idx >> 5;                  // 0..127
        int c4  = (idx & 31) * 4;            // 0..124
        float4 v = *(const float4*)&sOut[row * OP + c4];
        unsigned h01 = packbf(v.x, v.y);
        unsigned h23 = packbf(v.z, v.w);
        unsigned l01 = packbf(v.x - __uint_as_float(h01 << 16),
                              v.y - __uint_as_float(h01 & 0xffff0000u));
        unsigned l23 = packbf(v.z - __uint_as_float(h23 << 16),
                              v.w - __uint_as_float(h23 & 0xffff0000u));
        size_t o = (size_t)(m0 + row) * 512 + n0 + c4;
        uint2 hv = {h01, h23};
        uint2 lv = {l01, l23};
        *(uint2*)&Chi[o] = hv;
        *(uint2*)&Clo[o] = lv;
    }
}

// ---------------------------------------------------------------------------
// HMMA flash attention (UNCHANGED from round 16).
// ---------------------------------------------------------------------------
#define AP 72
#define ASMEM ((2 * 256 * AP + 4 * 2 * 64 * AP) * 2 + 4096 * 4)

__global__ __launch_bounds__(256) void attn_hmma(
    const int* __restrict__ mask,
    const __nv_bfloat16* __restrict__ qh, const __nv_bfloat16* __restrict__ ql,
    const __nv_bfloat16* __restrict__ kh, const __nv_bfloat16* __restrict__ kl,
    const __nv_bfloat16* __restrict__ vh, const __nv_bfloat16* __restrict__ vl)
{
    extern __shared__ __nv_bfloat16 sb16[];
    __nv_bfloat16* sQh = sb16;                    // [256][AP]
    __nv_bfloat16* sQl = sQh + 256 * AP;
    __nv_bfloat16* sKh = sQl + 256 * AP;          // [2][64][AP]
    __nv_bfloat16* sKl = sKh + 2 * 64 * AP;
    __nv_bfloat16* sVh = sKl + 2 * 64 * AP;       // [2][64][AP]
    __nv_bfloat16* sVl = sVh + 2 * 64 * AP;       // [2][64][AP]
    float* mnegAll = (float*)(sVl + 2 * 64 * AP); // [4096]

    const int tid = threadIdx.x, w = tid >> 5, lane = tid & 31;
    const int g = lane >> 2, tg = lane & 3;
    const int t0 = blockIdx.x * 256;
    const int h  = blockIdx.y;
    const int b  = blockIdx.z;

    for (int i = tid; i < Sv; i += 256)
        mnegAll[i] = (mask[b * Sv + i] != 0) ? 0.0f : -1e20f;

    #pragma unroll
    for (int it = 0; it < 8; it++) {
        int idx = tid + it * 256;
        int row = idx >> 3, sg = (idx & 7) * 8;
        size_t gq = (size_t)(b * Tv + t0 + row) * 512 + h * DKv + sg;
        *(uint4*)&sQh[row * AP + sg] = *(const uint4*)&qh[gq];
        *(uint4*)&sQl[row * AP + sg] = *(const uint4*)&ql[gq];
    }

    auto issueKV = [&](int c, int st) {
        int s0 = c * 64;
        #pragma unroll
        for (int it = 0; it < 2; it++) {
            int idx = tid + it * 256;
            int row = idx >> 3, sg = (idx & 7) * 8;
            size_t gk = (size_t)(b * Sv + s0 + row) * 512 + h * DKv + sg;
            cp16(&sKh[(st * 64 + row) * AP + sg], &kh[gk]);
            cp16(&sKl[(st * 64 + row) * AP + sg], &kl[gk]);
            cp16(&sVh[(st * 64 + row) * AP + sg], &vh[gk]);
            cp16(&sVl[(st * 64 + row) * AP + sg], &vl[gk]);
        }
    };

    const int aRow = w * 32 + ((lane >> 3) & 1) * 8 + (lane & 7);
    const int aK   = (lane >> 4) * 8;
    const int bRow = (lane >> 4) * 8 + (lane & 7);
    const int bK   = ((lane >> 3) & 1) * 8;
    const int vR   = (lane & 7) + ((lane >> 3) & 1) * 8;
    const int vC   = (lane >> 4) * 8;

    float o_acc[2][8][4];
    #pragma unroll
    for (int mi = 0; mi < 2; mi++)
        #pragma unroll
        for (int nd = 0; nd < 8; nd++)
            #pragma unroll
            for (int r = 0; r < 4; r++) o_acc[mi][nd][r] = 0.0f;
    float rowM[4], rowL[4];
    #pragma unroll
    for (int r = 0; r < 4; r++) { rowM[r] = -1e30f; rowL[r] = 0.0f; }

    issueKV(0, 0);
    cp_commit();

    const unsigned uQh = (unsigned)__cvta_generic_to_shared(sQh);
    const unsigned uQl = uQh + 256 * AP * 2;

    for (int c = 0; c < 64; c++) {
        const int st = c & 1;
        if (c < 63) { issueKV(c + 1, st ^ 1); cp_commit(); cp_wait<1>(); }
        else        { cp_wait<0>(); }
        __syncthreads();

        const unsigned uKh = (unsigned)__cvta_generic_to_shared(sKh + st * 64 * AP);
        const unsigned uKl = (unsigned)__cvta_generic_to_shared(sKl + st * 64 * AP);
        const unsigned uVh = (unsigned)__cvta_generic_to_shared(sVh + st * 64 * AP);
        const unsigned uVl = (unsigned)__cvta_generic_to_shared(sVl + st * 64 * AP);

        // ---- QK^T (3-term) ----
        float sc[2][8][4];
        #pragma unroll
        for (int mi = 0; mi < 2; mi++)
            #pragma unroll
            for (int ns = 0; ns < 8; ns++)
                #pragma unroll
                for (int r = 0; r < 4; r++) sc[mi][ns][r] = 0.0f;

        #pragma unroll
        for (int ks = 0; ks < 4; ks++) {
            unsigned ah[2][4], al[2][4];
            #pragma unroll
            for (int mi = 0; mi < 2; mi++) {
                ldm_x4(ah[mi], uQh + (unsigned)(((aRow + mi * 16) * AP + ks * 16 + aK) * 2));
                ldm_x4(al[mi], uQl + (unsigned)(((aRow + mi * 16) * AP + ks * 16 + aK) * 2));
            }
            #pragma unroll
            for (int pr = 0; pr < 4; pr++) {
                unsigned th[4], tl[4];
                ldm_x4(th, uKh + (unsigned)(((bRow + pr * 16) * AP + ks * 16 + bK) * 2));
                ldm_x4(tl, uKl + (unsigned)(((bRow + pr * 16) * AP + ks * 16 + bK) * 2));
                #pragma unroll
                for (int mi = 0; mi < 2; mi++) {
                    mma_bf16(sc[mi][2 * pr],     ah[mi], th);
                    mma_bf16(sc[mi][2 * pr + 1], ah[mi], th + 2);
                    mma_bf16(sc[mi][2 * pr],     ah[mi], tl);
                    mma_bf16(sc[mi][2 * pr + 1], ah[mi], tl + 2);
                    mma_bf16(sc[mi][2 * pr],     al[mi], th);
                    mma_bf16(sc[mi][2 * pr + 1], al[mi], th + 2);
                }
            }
        }

        // ---- scale + mask ----
        const int s0 = c * 64;
        #pragma unroll
        for (int ns = 0; ns < 8; ns++) {
            float2 mv = *(const float2*)&mnegAll[s0 + ns * 8 + tg * 2];
            #pragma unroll
            for (int mi = 0; mi < 2; mi++) {
                sc[mi][ns][0] = fmaf(sc[mi][ns][0], 0.125f, mv.x);
                sc[mi][ns][1] = fmaf(sc[mi][ns][1], 0.125f, mv.y);
                sc[mi][ns][2] = fmaf(sc[mi][ns][2], 0.125f, mv.x);
                sc[mi][ns][3] = fmaf(sc[mi][ns][3], 0.125f, mv.y);
            }
        }

        // ---- online softmax ----
        #pragma unroll
        for (int mi = 0; mi < 2; mi++) {
            #pragma unroll
            for (int hf = 0; hf < 2; hf++) {
                int r = mi * 2 + hf;
                float mx = -1e30f;
                #pragma unroll
                for (int ns = 0; ns < 8; ns++)
                    mx = fmaxf(mx, fmaxf(sc[mi][ns][hf * 2], sc[mi][ns][hf * 2 + 1]));
                mx = fmaxf(mx, __shfl_xor_sync(0xffffffffu, mx, 1, 4));
                mx = fmaxf(mx, __shfl_xor_sync(0xffffffffu, mx, 2, 4));
                float mnw = fmaxf(rowM[r], mx);
                float f = fast_exp(rowM[r] - mnw);
                rowM[r] = mnw;
                float se = 0.0f;
                #pragma unroll
                for (int ns = 0; ns < 8; ns++) {
                    float p0 = fast_exp(sc[mi][ns][hf * 2]     - mnw);
                    float p1 = fast_exp(sc[mi][ns][hf * 2 + 1] - mnw);
                    sc[mi][ns][hf * 2] = p0; sc[mi][ns][hf * 2 + 1] = p1;
                    se += p0 + p1;
                }
                se += __shfl_xor_sync(0xffffffffu, se, 1, 4);
                se += __shfl_xor_sync(0xffffffffu, se, 2, 4);
                rowL[r] = rowL[r] * f + se;
                #pragma unroll
                for (int nd = 0; nd < 8; nd++) {
                    o_acc[mi][nd][hf * 2]     *= f;
                    o_acc[mi][nd][hf * 2 + 1] *= f;
                }
            }
        }

        // ---- P @ V (3-term): P split in regs, V hi+lo from smem ----
        #pragma unroll
        for (int kp = 0; kp < 4; kp++) {
            unsigned pah[2][4], pal[2][4];
            #pragma unroll
            for (int mi = 0; mi < 2; mi++) {
                float e0 = sc[mi][2 * kp][0],     e1 = sc[mi][2 * kp][1];
                float e2 = sc[mi][2 * kp][2],     e3 = sc[mi][2 * kp][3];
                float e4 = sc[mi][2 * kp + 1][0], e5 = sc[mi][2 * kp + 1][1];
                float e6 = sc[mi][2 * kp + 1][2], e7 = sc[mi][2 * kp + 1][3];
                unsigned h0 = packbf(e0, e1), h1 = packbf(e2, e3);
                unsigned h2 = packbf(e4, e5), h3 = packbf(e6, e7);
                pah[mi][0] = h0; pah[mi][1] = h1; pah[mi][2] = h2; pah[mi][3] = h3;
                pal[mi][0] = packbf(e0 - __uint_as_float(h0 << 16),
                                    e1 - __uint_as_float(h0 & 0xffff0000u));
                pal[mi][1] = packbf(e2 - __uint_as_float(h1 << 16),
                                    e3 - __uint_as_float(h1 & 0xffff0000u));
                pal[mi][2] = packbf(e4 - __uint_as_float(h2 << 16),
                                    e5 - __uint_as_float(h2 & 0xffff0000u));
                pal[mi][3] = packbf(e6 - __uint_as_float(h3 << 16),
                                    e7 - __uint_as_float(h3 & 0xffff0000u));
            }
            #pragma unroll
            for (int np = 0; np < 4; np++) {
                unsigned th[4], tl[4];
                ldm_x4_t(th, uVh + (unsigned)(((kp * 16 + vR) * AP + np * 16 + vC) * 2));
                ldm_x4_t(tl, uVl + (unsigned)(((kp * 16 + vR) * AP + np * 16 + vC) * 2));
                #pragma unroll
                for (int mi = 0; mi < 2; mi++) {
                    mma_bf16(o_acc[mi][2 * np],     pah[mi], th);      // Phi*Vhi
                    mma_bf16(o_acc[mi][2 * np + 1], pah[mi], th + 2);
                    mma_bf16(o_acc[mi][2 * np],     pal[mi], th);      // Plo*Vhi
                    mma_bf16(o_acc[mi][2 * np + 1], pal[mi], th + 2);
                    mma_bf16(o_acc[mi][2 * np],     pah[mi], tl);      // Phi*Vlo
                    mma_bf16(o_acc[mi][2 * np + 1], pah[mi], tl + 2);
                }
            }
        }
        __syncthreads();
    }

    // ---- normalize + write ctx ----
    #pragma unroll
    for (int mi = 0; mi < 2; mi++) {
        float inv0 = 1.0f / rowL[mi * 2];
        float inv1 = 1.0f / rowL[mi * 2 + 1];
        int row = t0 + w * 32 + mi * 16 + g;
        #pragma unroll
        for (int nd = 0; nd < 8; nd++) {
            int col = h * DKv + nd * 8 + tg * 2;
            float2 v0 = {o_acc[mi][nd][0] * inv0, o_acc[mi][nd][1] * inv0};
            float2 v1 = {o_acc[mi][nd][2] * inv1, o_acc[mi][nd][3] * inv1};
            *(float2*)&g_ctx[(size_t)(b * Tv + row) * 512 + col]     = v0;
            *(float2*)&g_ctx[(size_t)(b * Tv + row + 8) * 512 + col] = v1;
        }
    }
}

// ---------------------------------------------------------------------------

extern "C" void kernel_launch(void* const* d_in, const int* in_sizes, int n_in,
                              void* d_out, int out_size)
{
    const float* inputs  = (const float*)d_in[0];
    const float* targets = (const float*)d_in[1];
    const int*   mask    = (const int*)d_in[2];     // bool widened to int32
    const float* Wq = (const float*)d_in[3];
    const float* bq = (const float*)d_in[4];
    const float* Wk = (const float*)d_in[5];
    const float* bk = (const float*)d_in[6];
    const float* Wv = (const float*)d_in[7];
    const float* bv = (const float*)d_in[8];
    const float* Wo = (const float*)d_in[9];
    const float* bo = (const float*)d_in[10];
    float* out = (float*)d_out;

    float* pC;
    cudaGetSymbolAddress((void**)&pC, g_ctx);
    __nv_bfloat16 *inH, *inL, *tgH, *tgL, *cxH, *cxL, *wH, *wL;
    __nv_bfloat16 *qH, *qL, *kH, *kL, *vH, *vL;
    cudaGetSymbolAddress((void**)&inH, g_in_hi);
    cudaGetSymbolAddress((void**)&inL, g_in_lo);
    cudaGetSymbolAddress((void**)&tgH, g_tg_hi);
    cudaGetSymbolAddress((void**)&tgL, g_tg_lo);
    cudaGetSymbolAddress((void**)&cxH, g_cx_hi);
    cudaGetSymbolAddress((void**)&cxL, g_cx_lo);
    cudaGetSymbolAddress((void**)&wH, g_w_hi);
    cudaGetSymbolAddress((void**)&wL, g_w_lo);
    cudaGetSymbolAddress((void**)&qH, g_qh);
    cudaGetSymbolAddress((void**)&qL, g_ql);
    cudaGetSymbolAddress((void**)&kH, g_kh);
    cudaGetSymbolAddress((void**)&kL, g_kl);
    cudaGetSymbolAddress((void**)&vH, g_vh);
    cudaGetSymbolAddress((void**)&vL, g_vl);

    cudaFuncSetAttribute(hmma_gemm, cudaFuncAttributeMaxDynamicSharedMemorySize, GSMEM);
    cudaFuncSetAttribute(hmma_gemm_b16, cudaFuncAttributeMaxDynamicSharedMemorySize, GSMEM);
    cudaFuncSetAttribute(attn_hmma, cudaFuncAttributeMaxDynamicSharedMemorySize, ASMEM);

    const int W_ELEMS = HIDv * HIDv;
    // ncu capture = 4th launch -> hmma_gemm_b16 K.
    cvt_kernel<<<(Bv * Sv * HIDv / 4 + 255) / 256, 256>>>(inputs, inH, inL, Bv * Sv * HIDv / 4);
    cvt_kernel<<<(W_ELEMS / 4 + 255) / 256, 256>>>(Wk, wH + 1 * W_ELEMS, wL + 1 * W_ELEMS, W_ELEMS / 4);
    cvt_kernel<<<(W_ELEMS / 4 + 255) / 256, 256>>>(Wv, wH + 2 * W_ELEMS, wL + 2 * W_ELEMS, W_ELEMS / 4);

    hmma_gemm_b16<<<dim3(4, Bv * Sv / 128), 256, GSMEM>>>(inH, inL, wH + 1 * W_ELEMS, wL + 1 * W_ELEMS, bk, kH, kL);
    hmma_gemm_b16<<<dim3(4, Bv * Sv / 128), 256, GSMEM>>>(inH, inL, wH + 2 * W_ELEMS, wL + 2 * W_ELEMS, bv, vH, vL);

    cvt_kernel<<<(Bv * Tv * HIDv / 4 + 255) / 256, 256>>>(targets, tgH, tgL, Bv * Tv * HIDv / 4);
    cvt_kernel<<<(W_ELEMS / 4 + 255) / 256, 256>>>(Wq, wH + 0 * W_ELEMS, wL + 0 * W_ELEMS, W_ELEMS / 4);
    hmma_gemm_b16<<<dim3(4, Bv * Tv / 128), 256, GSMEM>>>(tgH, tgL, wH + 0 * W_ELEMS, wL + 0 * W_ELEMS, bq, qH, qL);

    attn_hmma<<<dim3(Tv / 256, HEADSv, Bv), 256, ASMEM>>>(mask, qH, qL, kH, kL, vH, vL);

    cvt_kernel<<<(Bv * Tv * HIDv / 4 + 255) / 256, 256>>>(pC, cxH, cxL, Bv * Tv * HIDv / 4);
    cvt_kernel<<<(W_ELEMS / 4 + 255) / 256, 256>>>(Wo, wH + 3 * W_ELEMS, wL + 3 * W_ELEMS, W_ELEMS / 4);
    hmma_gemm<<<dim3(4, Bv * Tv / 128), 256, GSMEM>>>(cxH, cxL, wH + 3 * W_ELEMS, wL + 3 * W_ELEMS, bo, out);
}